// round 1
// baseline (speedup 1.0000x reference)
#include <cuda_runtime.h>
#include <math.h>

#define SS 2048
#define DD 768
#define HH 12
#define DHH 64
#define FF 3072
#define GG 16
#define W2W 256
#define NLAYERS 2

// ---------------- scratch (static device globals; no allocation) ----------------
__device__ float g_x[SS * DD];
__device__ float g_tmp[SS * DD];
__device__ float g_q[SS * DD];
__device__ float g_k[SS * DD];
__device__ float g_v[SS * DD];
__device__ float g_att[SS * DD];
__device__ float g_h[SS * FF];
__device__ float g_pooled[DD];

// ---------------- embedding ----------------
__global__ void embed_kernel(const int* __restrict__ ids,
                             const float* __restrict__ tok,
                             const float* __restrict__ pos,
                             float* __restrict__ out) {
    int s = blockIdx.x;
    int id = ids[s];
    const float* trow = tok + (size_t)id * DD;
    const float* prow = pos + (size_t)s * DD;
    float* orow = out + (size_t)s * DD;
    for (int d = threadIdx.x; d < DD; d += blockDim.x)
        orow[d] = trow[d] + prow[d];
}

// ---------------- layernorm: out = LN(inp (+ resid)) * g + b ----------------
__global__ void ln_kernel(const float* __restrict__ inp,
                          const float* __restrict__ resid,
                          const float* __restrict__ gw,
                          const float* __restrict__ bw,
                          float* __restrict__ out) {
    int s = blockIdx.x;
    int tid = threadIdx.x;
    __shared__ float red[256];

    float vloc[3];
    float sum = 0.0f;
#pragma unroll
    for (int i = 0; i < 3; i++) {
        int d = tid + i * 256;
        float val = inp[(size_t)s * DD + d];
        if (resid) val += resid[(size_t)s * DD + d];
        vloc[i] = val;
        sum += val;
    }
    red[tid] = sum;
    __syncthreads();
    for (int st = 128; st > 0; st >>= 1) {
        if (tid < st) red[tid] += red[tid + st];
        __syncthreads();
    }
    float mean = red[0] * (1.0f / DD);
    __syncthreads();

    float vs = 0.0f;
#pragma unroll
    for (int i = 0; i < 3; i++) {
        float dd = vloc[i] - mean;
        vs += dd * dd;
    }
    red[tid] = vs;
    __syncthreads();
    for (int st = 128; st > 0; st >>= 1) {
        if (tid < st) red[tid] += red[tid + st];
        __syncthreads();
    }
    float rstd = rsqrtf(red[0] * (1.0f / DD) + 1e-5f);

#pragma unroll
    for (int i = 0; i < 3; i++) {
        int d = tid + i * 256;
        out[(size_t)s * DD + d] = (vloc[i] - mean) * rstd * gw[d] + bw[d];
    }
}

// ---------------- tiled fp32 GEMM: C = A(MxK) @ B(KxN) + bias, epilogue variants ----------------
// EPI: 0 = +bias, 1 = (+bias)*scale, 2 = gelu(+bias) [tanh approximation, matches jax.nn.gelu]
#define BM 64
#define BN 64
#define BK 16

template <int EPI>
__global__ void __launch_bounds__(256)
gemm_kernel(const float* __restrict__ A, const float* __restrict__ B,
            const float* __restrict__ bias, float* __restrict__ C,
            int M, int N, int K, float scale) {
    __shared__ float As[BK][BM];
    __shared__ float Bs[BK][BN];

    int tid = threadIdx.x;
    int bm = blockIdx.y * BM;
    int bn = blockIdx.x * BN;
    int tm = (tid >> 4) * 4;   // 0..60
    int tn = (tid & 15) * 4;   // 0..60

    float acc[4][4] = {};

    for (int k0 = 0; k0 < K; k0 += BK) {
#pragma unroll
        for (int i = 0; i < 4; i++) {
            int idx = tid + i * 256;
            int r = idx >> 4, c = idx & 15;
            As[c][r] = A[(size_t)(bm + r) * K + k0 + c];
        }
#pragma unroll
        for (int i = 0; i < 4; i++) {
            int idx = tid + i * 256;
            int r = idx >> 6, c = idx & 63;
            Bs[r][c] = B[(size_t)(k0 + r) * N + bn + c];
        }
        __syncthreads();
#pragma unroll
        for (int kk = 0; kk < BK; kk++) {
            float4 a4 = *(const float4*)&As[kk][tm];
            float4 b4 = *(const float4*)&Bs[kk][tn];
            float av[4] = {a4.x, a4.y, a4.z, a4.w};
            float bv[4] = {b4.x, b4.y, b4.z, b4.w};
#pragma unroll
            for (int i = 0; i < 4; i++)
#pragma unroll
                for (int j = 0; j < 4; j++)
                    acc[i][j] = fmaf(av[i], bv[j], acc[i][j]);
        }
        __syncthreads();
    }

    float bb[4];
#pragma unroll
    for (int j = 0; j < 4; j++) bb[j] = bias[bn + tn + j];

#pragma unroll
    for (int i = 0; i < 4; i++) {
        float4 o;
        float* op = (float*)&o;
#pragma unroll
        for (int j = 0; j < 4; j++) {
            float val = acc[i][j] + bb[j];
            if (EPI == 1) val *= scale;
            if (EPI == 2) {
                float x3 = val * val * val;
                val = 0.5f * val * (1.0f + tanhf(0.7978845608028654f * (val + 0.044715f * x3)));
            }
            op[j] = val;
        }
        *(float4*)&C[(size_t)(bm + tm + i) * N + bn + tn] = o;
    }
}

// ---------------- attention: one block per (s, h) ----------------
// s <  G : full softmax over all S keys (the "global query" overwrite path)
// s >= G : keys = {0..G-1} ∪ {max(G, s-W2) .. min(S-1, s+W2)}
__global__ void __launch_bounds__(128)
attn_kernel(const float* __restrict__ q, const float* __restrict__ k,
            const float* __restrict__ v, float* __restrict__ out) {
    int s = blockIdx.x;
    int h = blockIdx.y;
    int tid = threadIdx.x;

    __shared__ float sc[SS];
    __shared__ float qs[DHH];
    __shared__ float red[128];
    __shared__ float pacc[2][DHH];

    if (tid < DHH) qs[tid] = q[(size_t)s * DD + h * DHH + tid];
    __syncthreads();

    bool full = (s < GG);
    int lo = 0, nk;
    if (full) {
        nk = SS;
    } else {
        lo = max(GG, s - W2W);
        int hi = min(SS - 1, s + W2W);
        nk = GG + (hi - lo + 1);
    }

    // scores
    for (int i = tid; i < nk; i += 128) {
        int kk = full ? i : (i < GG ? i : lo + (i - GG));
        const float4* kr = (const float4*)(k + (size_t)kk * DD + h * DHH);
        float dot = 0.0f;
#pragma unroll
        for (int d4 = 0; d4 < 16; d4++) {
            float4 kv = kr[d4];
            dot += qs[4 * d4 + 0] * kv.x + qs[4 * d4 + 1] * kv.y +
                   qs[4 * d4 + 2] * kv.z + qs[4 * d4 + 3] * kv.w;
        }
        sc[i] = dot;
    }
    __syncthreads();

    // max
    float m = -1e30f;
    for (int i = tid; i < nk; i += 128) m = fmaxf(m, sc[i]);
    red[tid] = m;
    __syncthreads();
    for (int st = 64; st > 0; st >>= 1) {
        if (tid < st) red[tid] = fmaxf(red[tid], red[tid + st]);
        __syncthreads();
    }
    m = red[0];
    __syncthreads();

    // exp + sum
    float ssum = 0.0f;
    for (int i = tid; i < nk; i += 128) {
        float p = __expf(sc[i] - m);
        sc[i] = p;
        ssum += p;
    }
    red[tid] = ssum;
    __syncthreads();
    for (int st = 64; st > 0; st >>= 1) {
        if (tid < st) red[tid] += red[tid + st];
        __syncthreads();
    }
    float inv = 1.0f / red[0];
    __syncthreads();

    // PV: 2 half-blocks of 64 threads, each half covers d=0..63 and half the keys
    int d = tid & 63;
    int half = tid >> 6;
    float acc = 0.0f;
    for (int i = half; i < nk; i += 2) {
        int kk = full ? i : (i < GG ? i : lo + (i - GG));
        acc = fmaf(sc[i], v[(size_t)kk * DD + h * DHH + d], acc);
    }
    pacc[half][d] = acc;
    __syncthreads();
    if (tid < DHH)
        out[(size_t)s * DD + h * DHH + tid] = (pacc[0][tid] + pacc[1][tid]) * inv;
}

// ---------------- pooling + classifier ----------------
__global__ void pool_kernel(const float* __restrict__ x, float* __restrict__ pooled) {
    int d = blockIdx.x;
    int tid = threadIdx.x;
    __shared__ float red[256];
    float sum = 0.0f;
    for (int s = tid; s < SS; s += 256) sum += x[(size_t)s * DD + d];
    red[tid] = sum;
    __syncthreads();
    for (int st = 128; st > 0; st >>= 1) {
        if (tid < st) red[tid] += red[tid + st];
        __syncthreads();
    }
    if (tid == 0) pooled[d] = red[0] * (1.0f / SS);
}

__global__ void final_kernel(const float* __restrict__ pooled,
                             const float* __restrict__ w,
                             const float* __restrict__ b,
                             float* __restrict__ out) {
    int tid = threadIdx.x;
    __shared__ float red[256];
    float sum = 0.0f;
    for (int d = tid; d < DD; d += 256) sum += pooled[d] * w[d];
    red[tid] = sum;
    __syncthreads();
    for (int st = 128; st > 0; st >>= 1) {
        if (tid < st) red[tid] += red[tid + st];
        __syncthreads();
    }
    if (tid == 0) out[0] = red[0] + b[0];
}

// ---------------- launch ----------------
extern "C" void kernel_launch(void* const* d_in, const int* in_sizes, int n_in,
                              void* d_out, int out_size) {
    const int*   ids     = (const int*)d_in[0];
    // d_in[1] = global_attention_mask (unused by reference)
    const float* emb_tok = (const float*)d_in[2];
    const float* emb_pos = (const float*)d_in[3];
    const float* ln_e_g  = (const float*)d_in[4];
    const float* ln_e_b  = (const float*)d_in[5];
    const float* wq      = (const float*)d_in[6];
    const float* bq      = (const float*)d_in[7];
    const float* wk      = (const float*)d_in[8];
    const float* bk      = (const float*)d_in[9];
    const float* wv      = (const float*)d_in[10];
    const float* bv      = (const float*)d_in[11];
    const float* wo      = (const float*)d_in[12];
    const float* bo      = (const float*)d_in[13];
    const float* ln1_g   = (const float*)d_in[14];
    const float* ln1_b   = (const float*)d_in[15];
    const float* w1      = (const float*)d_in[16];
    const float* b1      = (const float*)d_in[17];
    const float* w2m     = (const float*)d_in[18];
    const float* b2      = (const float*)d_in[19];
    const float* ln2_g   = (const float*)d_in[20];
    const float* ln2_b   = (const float*)d_in[21];
    const float* fc_w    = (const float*)d_in[22];
    const float* fc_b    = (const float*)d_in[23];

    float *x, *tmp, *q, *k, *v, *att, *h, *pooled;
    cudaGetSymbolAddress((void**)&x,      g_x);
    cudaGetSymbolAddress((void**)&tmp,    g_tmp);
    cudaGetSymbolAddress((void**)&q,      g_q);
    cudaGetSymbolAddress((void**)&k,      g_k);
    cudaGetSymbolAddress((void**)&v,      g_v);
    cudaGetSymbolAddress((void**)&att,    g_att);
    cudaGetSymbolAddress((void**)&h,      g_h);
    cudaGetSymbolAddress((void**)&pooled, g_pooled);

    embed_kernel<<<SS, 256>>>(ids, emb_tok, emb_pos, tmp);
    ln_kernel<<<SS, 256>>>(tmp, nullptr, ln_e_g, ln_e_b, x);

    dim3 gD(DD / BN, SS / BM);   // (12, 32)
    dim3 gF(FF / BN, SS / BM);   // (48, 32)

    for (int l = 0; l < NLAYERS; l++) {
        size_t woff = (size_t)l * DD * DD;
        size_t foff1 = (size_t)l * DD * FF;
        size_t foff2 = (size_t)l * FF * DD;

        gemm_kernel<1><<<gD, 256>>>(x, wq + woff, bq + l * DD, q, SS, DD, DD, 0.125f);
        gemm_kernel<0><<<gD, 256>>>(x, wk + woff, bk + l * DD, k, SS, DD, DD, 1.0f);
        gemm_kernel<0><<<gD, 256>>>(x, wv + woff, bv + l * DD, v, SS, DD, DD, 1.0f);

        attn_kernel<<<dim3(SS, HH), 128>>>(q, k, v, att);

        gemm_kernel<0><<<gD, 256>>>(att, wo + woff, bo + l * DD, tmp, SS, DD, DD, 1.0f);
        ln_kernel<<<SS, 256>>>(tmp, x, ln1_g + l * DD, ln1_b + l * DD, x);

        gemm_kernel<2><<<gF, 256>>>(x, w1 + foff1, b1 + l * FF, h, SS, FF, DD, 1.0f);
        gemm_kernel<0><<<gD, 256>>>(h, w2m + foff2, b2 + l * DD, tmp, SS, DD, FF, 1.0f);
        ln_kernel<<<SS, 256>>>(tmp, x, ln2_g + l * DD, ln2_b + l * DD, x);
    }

    pool_kernel<<<DD, 256>>>(x, pooled);
    final_kernel<<<1, 256>>>(pooled, fc_w, fc_b, (float*)d_out);
}

// round 2
// speedup vs baseline: 1.1549x; 1.1549x over previous
#include <cuda_runtime.h>
#include <math.h>

#define SS 2048
#define DD 768
#define HH 12
#define DHH 64
#define FF 3072
#define GG 16
#define W2W 256
#define NLAYERS 2

// ---------------- scratch (static device globals; no allocation) ----------------
__device__ float g_x[SS * DD];
__device__ float g_tmp[SS * DD];
__device__ float g_q[SS * DD];
__device__ float g_k[SS * DD];
__device__ float g_v[SS * DD];
__device__ float g_att[SS * DD];
__device__ float g_h[SS * FF];
__device__ float g_pooled[DD];

// ---------------- embedding ----------------
__global__ void embed_kernel(const int* __restrict__ ids,
                             const float* __restrict__ tok,
                             const float* __restrict__ pos,
                             float* __restrict__ out) {
    int s = blockIdx.x;
    int id = ids[s];
    const float* trow = tok + (size_t)id * DD;
    const float* prow = pos + (size_t)s * DD;
    float* orow = out + (size_t)s * DD;
    for (int d = threadIdx.x; d < DD; d += blockDim.x)
        orow[d] = trow[d] + prow[d];
}

// ---------------- layernorm: out = LN(inp (+ resid)) * g + b ----------------
__global__ void ln_kernel(const float* __restrict__ inp,
                          const float* __restrict__ resid,
                          const float* __restrict__ gw,
                          const float* __restrict__ bw,
                          float* __restrict__ out) {
    int s = blockIdx.x;
    int tid = threadIdx.x;
    __shared__ float red[256];

    float vloc[3];
    float sum = 0.0f;
#pragma unroll
    for (int i = 0; i < 3; i++) {
        int d = tid + i * 256;
        float val = inp[(size_t)s * DD + d];
        if (resid) val += resid[(size_t)s * DD + d];
        vloc[i] = val;
        sum += val;
    }
    red[tid] = sum;
    __syncthreads();
    for (int st = 128; st > 0; st >>= 1) {
        if (tid < st) red[tid] += red[tid + st];
        __syncthreads();
    }
    float mean = red[0] * (1.0f / DD);
    __syncthreads();

    float vs = 0.0f;
#pragma unroll
    for (int i = 0; i < 3; i++) {
        float dd = vloc[i] - mean;
        vs += dd * dd;
    }
    red[tid] = vs;
    __syncthreads();
    for (int st = 128; st > 0; st >>= 1) {
        if (tid < st) red[tid] += red[tid + st];
        __syncthreads();
    }
    float rstd = rsqrtf(red[0] * (1.0f / DD) + 1e-5f);

#pragma unroll
    for (int i = 0; i < 3; i++) {
        int d = tid + i * 256;
        out[(size_t)s * DD + d] = (vloc[i] - mean) * rstd * gw[d] + bw[d];
    }
}

// ---------------- tiled fp32 GEMM v2: 64x128 block tile, 8x8 micro-tile ----------------
// EPI: 0 = +bias, 1 = (+bias)*scale, 2 = gelu(+bias) [tanh approximation, matches jax.nn.gelu]
#define BM 64
#define BN 128
#define BK 16
#define BMP (BM + 4)   // padded row for As to tame store bank conflicts

template <int EPI>
__global__ void __launch_bounds__(128)
gemm_kernel(const float* __restrict__ A, const float* __restrict__ B,
            const float* __restrict__ bias, float* __restrict__ C,
            int M, int N, int K, float scale) {
    __shared__ float As[BK][BMP];   // transposed A tile: As[k][m]
    __shared__ float Bs[BK][BN];

    int tid = threadIdx.x;
    int bm = blockIdx.y * BM;
    int bn = blockIdx.x * BN;
    int ty = tid >> 4;           // 0..7  (m dim)
    int tx = tid & 15;           // 0..15 (n dim)
    int tm = ty * 8;
    int tn = tx * 8;

    float acc[8][8] = {};

    for (int k0 = 0; k0 < K; k0 += BK) {
        // load A tile 64x16 (2 float4 per thread), store transposed
#pragma unroll
        for (int j = 0; j < 2; j++) {
            int idx = tid + j * 128;
            int r = idx >> 2;
            int c = (idx & 3) * 4;
            float4 a = *(const float4*)&A[(size_t)(bm + r) * K + k0 + c];
            As[c + 0][r] = a.x;
            As[c + 1][r] = a.y;
            As[c + 2][r] = a.z;
            As[c + 3][r] = a.w;
        }
        // load B tile 16x128 (4 float4 per thread), direct
#pragma unroll
        for (int j = 0; j < 4; j++) {
            int idx = tid + j * 128;
            int r = idx >> 5;
            int c = (idx & 31) * 4;
            *(float4*)&Bs[r][c] = *(const float4*)&B[(size_t)(k0 + r) * N + bn + c];
        }
        __syncthreads();

#pragma unroll
        for (int kk = 0; kk < BK; kk++) {
            float a[8], b[8];
            *(float4*)&a[0] = *(const float4*)&As[kk][tm];
            *(float4*)&a[4] = *(const float4*)&As[kk][tm + 4];
            *(float4*)&b[0] = *(const float4*)&Bs[kk][tn];
            *(float4*)&b[4] = *(const float4*)&Bs[kk][tn + 4];
#pragma unroll
            for (int i = 0; i < 8; i++)
#pragma unroll
                for (int j = 0; j < 8; j++)
                    acc[i][j] = fmaf(a[i], b[j], acc[i][j]);
        }
        __syncthreads();
    }

    float bb[8];
    *(float4*)&bb[0] = *(const float4*)&bias[bn + tn];
    *(float4*)&bb[4] = *(const float4*)&bias[bn + tn + 4];

#pragma unroll
    for (int i = 0; i < 8; i++) {
        float o[8];
#pragma unroll
        for (int j = 0; j < 8; j++) {
            float val = acc[i][j] + bb[j];
            if (EPI == 1) val *= scale;
            if (EPI == 2) {
                float x3 = val * val * val;
                val = 0.5f * val * (1.0f + tanhf(0.7978845608028654f * (val + 0.044715f * x3)));
            }
            o[j] = val;
        }
        float* crow = &C[(size_t)(bm + tm + i) * N + bn + tn];
        *(float4*)&crow[0] = *(float4*)&o[0];
        *(float4*)&crow[4] = *(float4*)&o[4];
    }
}

// ---------------- attention: one block per (s, h) ----------------
// s <  G : full softmax over all S keys (the "global query" overwrite path)
// s >= G : keys = {0..G-1} ∪ {max(G, s-W2) .. min(S-1, s+W2)}
__global__ void __launch_bounds__(128)
attn_kernel(const float* __restrict__ q, const float* __restrict__ k,
            const float* __restrict__ v, float* __restrict__ out) {
    int s = blockIdx.x;
    int h = blockIdx.y;
    int tid = threadIdx.x;

    __shared__ float sc[SS];
    __shared__ float qs[DHH];
    __shared__ float red[128];
    __shared__ float pacc[2][DHH];

    if (tid < DHH) qs[tid] = q[(size_t)s * DD + h * DHH + tid];
    __syncthreads();

    bool full = (s < GG);
    int lo = 0, nk;
    if (full) {
        nk = SS;
    } else {
        lo = max(GG, s - W2W);
        int hi = min(SS - 1, s + W2W);
        nk = GG + (hi - lo + 1);
    }

    // scores
    for (int i = tid; i < nk; i += 128) {
        int kk = full ? i : (i < GG ? i : lo + (i - GG));
        const float4* kr = (const float4*)(k + (size_t)kk * DD + h * DHH);
        float dot = 0.0f;
#pragma unroll
        for (int d4 = 0; d4 < 16; d4++) {
            float4 kv = kr[d4];
            dot += qs[4 * d4 + 0] * kv.x + qs[4 * d4 + 1] * kv.y +
                   qs[4 * d4 + 2] * kv.z + qs[4 * d4 + 3] * kv.w;
        }
        sc[i] = dot;
    }
    __syncthreads();

    // max
    float m = -1e30f;
    for (int i = tid; i < nk; i += 128) m = fmaxf(m, sc[i]);
    red[tid] = m;
    __syncthreads();
    for (int st = 64; st > 0; st >>= 1) {
        if (tid < st) red[tid] = fmaxf(red[tid], red[tid + st]);
        __syncthreads();
    }
    m = red[0];
    __syncthreads();

    // exp + sum
    float ssum = 0.0f;
    for (int i = tid; i < nk; i += 128) {
        float p = __expf(sc[i] - m);
        sc[i] = p;
        ssum += p;
    }
    red[tid] = ssum;
    __syncthreads();
    for (int st = 64; st > 0; st >>= 1) {
        if (tid < st) red[tid] += red[tid + st];
        __syncthreads();
    }
    float inv = 1.0f / red[0];
    __syncthreads();

    // PV: 2 half-blocks of 64 threads, each half covers d=0..63 and half the keys
    int d = tid & 63;
    int half = tid >> 6;
    float acc = 0.0f;
    for (int i = half; i < nk; i += 2) {
        int kk = full ? i : (i < GG ? i : lo + (i - GG));
        acc = fmaf(sc[i], v[(size_t)kk * DD + h * DHH + d], acc);
    }
    pacc[half][d] = acc;
    __syncthreads();
    if (tid < DHH)
        out[(size_t)s * DD + h * DHH + tid] = (pacc[0][tid] + pacc[1][tid]) * inv;
}

// ---------------- pooling + classifier ----------------
__global__ void pool_kernel(const float* __restrict__ x, float* __restrict__ pooled) {
    int d = blockIdx.x;
    int tid = threadIdx.x;
    __shared__ float red[256];
    float sum = 0.0f;
    for (int s = tid; s < SS; s += 256) sum += x[(size_t)s * DD + d];
    red[tid] = sum;
    __syncthreads();
    for (int st = 128; st > 0; st >>= 1) {
        if (tid < st) red[tid] += red[tid + st];
        __syncthreads();
    }
    if (tid == 0) pooled[d] = red[0] * (1.0f / SS);
}

__global__ void final_kernel(const float* __restrict__ pooled,
                             const float* __restrict__ w,
                             const float* __restrict__ b,
                             float* __restrict__ out) {
    int tid = threadIdx.x;
    __shared__ float red[256];
    float sum = 0.0f;
    for (int d = tid; d < DD; d += 256) sum += pooled[d] * w[d];
    red[tid] = sum;
    __syncthreads();
    for (int st = 128; st > 0; st >>= 1) {
        if (tid < st) red[tid] += red[tid + st];
        __syncthreads();
    }
    if (tid == 0) out[0] = red[0] + b[0];
}

// ---------------- launch ----------------
extern "C" void kernel_launch(void* const* d_in, const int* in_sizes, int n_in,
                              void* d_out, int out_size) {
    const int*   ids     = (const int*)d_in[0];
    // d_in[1] = global_attention_mask (unused by reference)
    const float* emb_tok = (const float*)d_in[2];
    const float* emb_pos = (const float*)d_in[3];
    const float* ln_e_g  = (const float*)d_in[4];
    const float* ln_e_b  = (const float*)d_in[5];
    const float* wq      = (const float*)d_in[6];
    const float* bq      = (const float*)d_in[7];
    const float* wk      = (const float*)d_in[8];
    const float* bk      = (const float*)d_in[9];
    const float* wv      = (const float*)d_in[10];
    const float* bv      = (const float*)d_in[11];
    const float* wo      = (const float*)d_in[12];
    const float* bo      = (const float*)d_in[13];
    const float* ln1_g   = (const float*)d_in[14];
    const float* ln1_b   = (const float*)d_in[15];
    const float* w1      = (const float*)d_in[16];
    const float* b1      = (const float*)d_in[17];
    const float* w2m     = (const float*)d_in[18];
    const float* b2      = (const float*)d_in[19];
    const float* ln2_g   = (const float*)d_in[20];
    const float* ln2_b   = (const float*)d_in[21];
    const float* fc_w    = (const float*)d_in[22];
    const float* fc_b    = (const float*)d_in[23];

    float *x, *tmp, *q, *k, *v, *att, *h, *pooled;
    cudaGetSymbolAddress((void**)&x,      g_x);
    cudaGetSymbolAddress((void**)&tmp,    g_tmp);
    cudaGetSymbolAddress((void**)&q,      g_q);
    cudaGetSymbolAddress((void**)&k,      g_k);
    cudaGetSymbolAddress((void**)&v,      g_v);
    cudaGetSymbolAddress((void**)&att,    g_att);
    cudaGetSymbolAddress((void**)&h,      g_h);
    cudaGetSymbolAddress((void**)&pooled, g_pooled);

    embed_kernel<<<SS, 256>>>(ids, emb_tok, emb_pos, tmp);
    ln_kernel<<<SS, 256>>>(tmp, nullptr, ln_e_g, ln_e_b, x);

    dim3 gD(DD / BN, SS / BM);   // (6, 32)  = 192 blocks
    dim3 gF(FF / BN, SS / BM);   // (24, 32) = 768 blocks

    for (int l = 0; l < NLAYERS; l++) {
        size_t woff = (size_t)l * DD * DD;
        size_t foff1 = (size_t)l * DD * FF;
        size_t foff2 = (size_t)l * FF * DD;

        gemm_kernel<1><<<gD, 128>>>(x, wq + woff, bq + l * DD, q, SS, DD, DD, 0.125f);
        gemm_kernel<0><<<gD, 128>>>(x, wk + woff, bk + l * DD, k, SS, DD, DD, 1.0f);
        gemm_kernel<0><<<gD, 128>>>(x, wv + woff, bv + l * DD, v, SS, DD, DD, 1.0f);

        attn_kernel<<<dim3(SS, HH), 128>>>(q, k, v, att);

        gemm_kernel<0><<<gD, 128>>>(att, wo + woff, bo + l * DD, tmp, SS, DD, DD, 1.0f);
        ln_kernel<<<SS, 256>>>(tmp, x, ln1_g + l * DD, ln1_b + l * DD, x);

        gemm_kernel<2><<<gF, 128>>>(x, w1 + foff1, b1 + l * FF, h, SS, FF, DD, 1.0f);
        gemm_kernel<0><<<gD, 128>>>(h, w2m + foff2, b2 + l * DD, tmp, SS, DD, FF, 1.0f);
        ln_kernel<<<SS, 256>>>(tmp, x, ln2_g + l * DD, ln2_b + l * DD, x);
    }

    pool_kernel<<<DD, 256>>>(x, pooled);
    final_kernel<<<1, 256>>>(pooled, fc_w, fc_b, (float*)d_out);
}

// round 3
// speedup vs baseline: 1.2816x; 1.1097x over previous
#include <cuda_runtime.h>
#include <math.h>

#define SS 2048
#define DD 768
#define HH 12
#define DHH 64
#define FF 3072
#define GG 16
#define W2W 256
#define NLAYERS 2

// ---------------- scratch (static device globals; no allocation) ----------------
__device__ float g_x[SS * DD];
__device__ float g_tmp[2 * SS * DD];   // holds split-K partials [part0 | part1]
__device__ float g_q[SS * DD];
__device__ float g_k[SS * DD];
__device__ float g_v[SS * DD];
__device__ float g_att[SS * DD];
__device__ float g_h[SS * FF];
__device__ float g_pooled[DD];

// ---------------- embedding ----------------
__global__ void embed_kernel(const int* __restrict__ ids,
                             const float* __restrict__ tok,
                             const float* __restrict__ pos,
                             float* __restrict__ out) {
    int s = blockIdx.x;
    int id = ids[s];
    const float* trow = tok + (size_t)id * DD;
    const float* prow = pos + (size_t)s * DD;
    float* orow = out + (size_t)s * DD;
    for (int d = threadIdx.x; d < DD; d += blockDim.x)
        orow[d] = trow[d] + prow[d];
}

// ---------------- layernorm: out = LN(inp (+ inp2) (+ resid)) * g + b ----------------
__global__ void ln_kernel(const float* __restrict__ inp,
                          const float* __restrict__ inp2,
                          const float* __restrict__ resid,
                          const float* __restrict__ gw,
                          const float* __restrict__ bw,
                          float* __restrict__ out) {
    int s = blockIdx.x;
    int tid = threadIdx.x;
    __shared__ float red[256];

    float vloc[3];
    float sum = 0.0f;
#pragma unroll
    for (int i = 0; i < 3; i++) {
        int d = tid + i * 256;
        float val = inp[(size_t)s * DD + d];
        if (inp2)  val += inp2[(size_t)s * DD + d];
        if (resid) val += resid[(size_t)s * DD + d];
        vloc[i] = val;
        sum += val;
    }
    red[tid] = sum;
    __syncthreads();
    for (int st = 128; st > 0; st >>= 1) {
        if (tid < st) red[tid] += red[tid + st];
        __syncthreads();
    }
    float mean = red[0] * (1.0f / DD);
    __syncthreads();

    float vs = 0.0f;
#pragma unroll
    for (int i = 0; i < 3; i++) {
        float dd = vloc[i] - mean;
        vs += dd * dd;
    }
    red[tid] = vs;
    __syncthreads();
    for (int st = 128; st > 0; st >>= 1) {
        if (tid < st) red[tid] += red[tid + st];
        __syncthreads();
    }
    float rstd = rsqrtf(red[0] * (1.0f / DD) + 1e-5f);

#pragma unroll
    for (int i = 0; i < 3; i++) {
        int d = tid + i * 256;
        out[(size_t)s * DD + d] = (vloc[i] - mean) * rstd * gw[d] + bw[d];
    }
}

// ---------------- GEMM core: 64x128 tile, 8x8 micro, register-staged prefetch ----------------
#define BM 64
#define BN 128
#define BK 16
#define BMP (BM + 4)

// Shared inner machinery: computes acc for A[bm: bm+64, kStart:kEnd] @ B[kStart:kEnd, bn: bn+128]
#define GEMM_BODY(Aptr, Bptr, Kld, Nld, kStart, kEnd)                                   \
    {                                                                                   \
        int k0p = (kStart);                                                             \
        _Pragma("unroll")                                                               \
        for (int j = 0; j < 2; j++) {                                                   \
            int idx = tid + j * 128; int r = idx >> 2; int c = (idx & 3) * 4;           \
            pa[j] = *(const float4*)&(Aptr)[(size_t)(bm + r) * (Kld) + k0p + c];        \
        }                                                                               \
        _Pragma("unroll")                                                               \
        for (int j = 0; j < 4; j++) {                                                   \
            int idx = tid + j * 128; int r = idx >> 5; int c = (idx & 31) * 4;          \
            pb[j] = *(const float4*)&(Bptr)[(size_t)(k0p + r) * (Nld) + bn + c];        \
        }                                                                               \
    }                                                                                   \
    for (int k0 = (kStart); k0 < (kEnd); k0 += BK) {                                    \
        _Pragma("unroll")                                                               \
        for (int j = 0; j < 2; j++) {                                                   \
            int idx = tid + j * 128; int r = idx >> 2; int c = (idx & 3) * 4;           \
            As[c + 0][r] = pa[j].x; As[c + 1][r] = pa[j].y;                             \
            As[c + 2][r] = pa[j].z; As[c + 3][r] = pa[j].w;                             \
        }                                                                               \
        _Pragma("unroll")                                                               \
        for (int j = 0; j < 4; j++) {                                                   \
            int idx = tid + j * 128; int r = idx >> 5; int c = (idx & 31) * 4;          \
            *(float4*)&Bs[r][c] = pb[j];                                                \
        }                                                                               \
        __syncthreads();                                                                \
        int kn = k0 + BK;                                                               \
        if (kn < (kEnd)) {                                                              \
            _Pragma("unroll")                                                           \
            for (int j = 0; j < 2; j++) {                                               \
                int idx = tid + j * 128; int r = idx >> 2; int c = (idx & 3) * 4;       \
                pa[j] = *(const float4*)&(Aptr)[(size_t)(bm + r) * (Kld) + kn + c];     \
            }                                                                           \
            _Pragma("unroll")                                                           \
            for (int j = 0; j < 4; j++) {                                               \
                int idx = tid + j * 128; int r = idx >> 5; int c = (idx & 31) * 4;      \
                pb[j] = *(const float4*)&(Bptr)[(size_t)(kn + r) * (Nld) + bn + c];     \
            }                                                                           \
        }                                                                               \
        _Pragma("unroll")                                                               \
        for (int kk = 0; kk < BK; kk++) {                                               \
            float a[8], b[8];                                                           \
            *(float4*)&a[0] = *(const float4*)&As[kk][tm];                              \
            *(float4*)&a[4] = *(const float4*)&As[kk][tm + 4];                          \
            *(float4*)&b[0] = *(const float4*)&Bs[kk][tn];                              \
            *(float4*)&b[4] = *(const float4*)&Bs[kk][tn + 4];                          \
            _Pragma("unroll")                                                           \
            for (int i = 0; i < 8; i++)                                                 \
                _Pragma("unroll")                                                       \
                for (int j = 0; j < 8; j++)                                             \
                    acc[i][j] = fmaf(a[i], b[j], acc[i][j]);                            \
        }                                                                               \
        __syncthreads();                                                                \
    }

// Generic GEMM with optional split-K over blockIdx.z.
// EPI: 0 = +bias, 2 = gelu(+bias). Split parts (z>0) skip bias; partials summed in ln.
template <int EPI>
__global__ void __launch_bounds__(128)
gemm_kernel(const float* __restrict__ A, const float* __restrict__ B,
            const float* __restrict__ bias, float* __restrict__ C,
            int M, int N, int K, int ksplit) {
    __shared__ float As[BK][BMP];
    __shared__ float Bs[BK][BN];

    int tid = threadIdx.x;
    int bm = blockIdx.y * BM;
    int bn = blockIdx.x * BN;
    int z = blockIdx.z;
    int kStart = z * ksplit;
    int kEnd = min(K, kStart + ksplit);
    C += (size_t)z * M * N;

    int ty = tid >> 4, tx = tid & 15;
    int tm = ty * 8, tn = tx * 8;
    float acc[8][8] = {};
    float4 pa[2], pb[4];

    GEMM_BODY(A, B, K, N, kStart, kEnd)

    float bb[8] = {};
    if (z == 0) {
        *(float4*)&bb[0] = *(const float4*)&bias[bn + tn];
        *(float4*)&bb[4] = *(const float4*)&bias[bn + tn + 4];
    }

#pragma unroll
    for (int i = 0; i < 8; i++) {
        float o[8];
#pragma unroll
        for (int j = 0; j < 8; j++) {
            float val = acc[i][j] + bb[j];
            if (EPI == 2) {
                float x3 = val * val * val;
                val = 0.5f * val * (1.0f + tanhf(0.7978845608028654f * (val + 0.044715f * x3)));
            }
            o[j] = val;
        }
        float* crow = &C[(size_t)(bm + tm + i) * N + bn + tn];
        *(float4*)&crow[0] = *(float4*)&o[0];
        *(float4*)&crow[4] = *(float4*)&o[4];
    }
}

// Fused QKV projection: grid.x = 18 tiles; tiles [0,6)->Q, [6,12)->K, [12,18)->V.
__global__ void __launch_bounds__(128)
qkv_kernel(const float* __restrict__ X,
           const float* __restrict__ Wq, const float* __restrict__ Wk, const float* __restrict__ Wv,
           const float* __restrict__ Bq, const float* __restrict__ Bk, const float* __restrict__ Bv,
           float* __restrict__ Q, float* __restrict__ Ko, float* __restrict__ V) {
    __shared__ float As[BK][BMP];
    __shared__ float Bs[BK][BN];

    int tid = threadIdx.x;
    int bm = blockIdx.y * BM;
    int which = blockIdx.x / 6;
    int bn = (blockIdx.x % 6) * BN;

    const float* B   = (which == 0) ? Wq : (which == 1) ? Wk : Wv;
    const float* bia = (which == 0) ? Bq : (which == 1) ? Bk : Bv;
    float*       C   = (which == 0) ? Q  : (which == 1) ? Ko : V;
    float scale = (which == 0) ? 0.125f : 1.0f;

    int ty = tid >> 4, tx = tid & 15;
    int tm = ty * 8, tn = tx * 8;
    float acc[8][8] = {};
    float4 pa[2], pb[4];

    GEMM_BODY(X, B, DD, DD, 0, DD)

    float bb[8];
    *(float4*)&bb[0] = *(const float4*)&bia[bn + tn];
    *(float4*)&bb[4] = *(const float4*)&bia[bn + tn + 4];

#pragma unroll
    for (int i = 0; i < 8; i++) {
        float o[8];
#pragma unroll
        for (int j = 0; j < 8; j++)
            o[j] = (acc[i][j] + bb[j]) * scale;
        float* crow = &C[(size_t)(bm + tm + i) * DD + bn + tn];
        *(float4*)&crow[0] = *(float4*)&o[0];
        *(float4*)&crow[4] = *(float4*)&o[4];
    }
}

// ---------------- attention: one block per (s, h) ----------------
__global__ void __launch_bounds__(128)
attn_kernel(const float* __restrict__ q, const float* __restrict__ k,
            const float* __restrict__ v, float* __restrict__ out) {
    int s = blockIdx.x;
    int h = blockIdx.y;
    int tid = threadIdx.x;

    __shared__ float sc[SS];
    __shared__ float qs[DHH];
    __shared__ float red[128];
    __shared__ float pacc[2][DHH];

    if (tid < DHH) qs[tid] = q[(size_t)s * DD + h * DHH + tid];
    __syncthreads();

    bool full = (s < GG);
    int lo = 0, nk;
    if (full) {
        nk = SS;
    } else {
        lo = max(GG, s - W2W);
        int hi = min(SS - 1, s + W2W);
        nk = GG + (hi - lo + 1);
    }

    for (int i = tid; i < nk; i += 128) {
        int kk = full ? i : (i < GG ? i : lo + (i - GG));
        const float4* kr = (const float4*)(k + (size_t)kk * DD + h * DHH);
        float dot = 0.0f;
#pragma unroll
        for (int d4 = 0; d4 < 16; d4++) {
            float4 kv = kr[d4];
            dot += qs[4 * d4 + 0] * kv.x + qs[4 * d4 + 1] * kv.y +
                   qs[4 * d4 + 2] * kv.z + qs[4 * d4 + 3] * kv.w;
        }
        sc[i] = dot;
    }
    __syncthreads();

    float m = -1e30f;
    for (int i = tid; i < nk; i += 128) m = fmaxf(m, sc[i]);
    red[tid] = m;
    __syncthreads();
    for (int st = 64; st > 0; st >>= 1) {
        if (tid < st) red[tid] = fmaxf(red[tid], red[tid + st]);
        __syncthreads();
    }
    m = red[0];
    __syncthreads();

    float ssum = 0.0f;
    for (int i = tid; i < nk; i += 128) {
        float p = __expf(sc[i] - m);
        sc[i] = p;
        ssum += p;
    }
    red[tid] = ssum;
    __syncthreads();
    for (int st = 64; st > 0; st >>= 1) {
        if (tid < st) red[tid] += red[tid + st];
        __syncthreads();
    }
    float inv = 1.0f / red[0];
    __syncthreads();

    int d = tid & 63;
    int half = tid >> 6;
    float acc = 0.0f;
    for (int i = half; i < nk; i += 2) {
        int kk = full ? i : (i < GG ? i : lo + (i - GG));
        acc = fmaf(sc[i], v[(size_t)kk * DD + h * DHH + d], acc);
    }
    pacc[half][d] = acc;
    __syncthreads();
    if (tid < DHH)
        out[(size_t)s * DD + h * DHH + tid] = (pacc[0][tid] + pacc[1][tid]) * inv;
}

// ---------------- pooling + classifier ----------------
__global__ void pool_kernel(const float* __restrict__ x, float* __restrict__ pooled) {
    int d = blockIdx.x;
    int tid = threadIdx.x;
    __shared__ float red[256];
    float sum = 0.0f;
    for (int s = tid; s < SS; s += 256) sum += x[(size_t)s * DD + d];
    red[tid] = sum;
    __syncthreads();
    for (int st = 128; st > 0; st >>= 1) {
        if (tid < st) red[tid] += red[tid + st];
        __syncthreads();
    }
    if (tid == 0) pooled[d] = red[0] * (1.0f / SS);
}

__global__ void final_kernel(const float* __restrict__ pooled,
                             const float* __restrict__ w,
                             const float* __restrict__ b,
                             float* __restrict__ out) {
    int tid = threadIdx.x;
    __shared__ float red[256];
    float sum = 0.0f;
    for (int d = tid; d < DD; d += 256) sum += pooled[d] * w[d];
    red[tid] = sum;
    __syncthreads();
    for (int st = 128; st > 0; st >>= 1) {
        if (tid < st) red[tid] += red[tid + st];
        __syncthreads();
    }
    if (tid == 0) out[0] = red[0] + b[0];
}

// ---------------- launch ----------------
extern "C" void kernel_launch(void* const* d_in, const int* in_sizes, int n_in,
                              void* d_out, int out_size) {
    const int*   ids     = (const int*)d_in[0];
    const float* emb_tok = (const float*)d_in[2];
    const float* emb_pos = (const float*)d_in[3];
    const float* ln_e_g  = (const float*)d_in[4];
    const float* ln_e_b  = (const float*)d_in[5];
    const float* wq      = (const float*)d_in[6];
    const float* bq      = (const float*)d_in[7];
    const float* wk      = (const float*)d_in[8];
    const float* bk      = (const float*)d_in[9];
    const float* wv      = (const float*)d_in[10];
    const float* bv      = (const float*)d_in[11];
    const float* wo      = (const float*)d_in[12];
    const float* bo      = (const float*)d_in[13];
    const float* ln1_g   = (const float*)d_in[14];
    const float* ln1_b   = (const float*)d_in[15];
    const float* w1      = (const float*)d_in[16];
    const float* b1      = (const float*)d_in[17];
    const float* w2m     = (const float*)d_in[18];
    const float* b2      = (const float*)d_in[19];
    const float* ln2_g   = (const float*)d_in[20];
    const float* ln2_b   = (const float*)d_in[21];
    const float* fc_w    = (const float*)d_in[22];
    const float* fc_b    = (const float*)d_in[23];

    float *x, *tmp, *q, *k, *v, *att, *h, *pooled;
    cudaGetSymbolAddress((void**)&x,      g_x);
    cudaGetSymbolAddress((void**)&tmp,    g_tmp);
    cudaGetSymbolAddress((void**)&q,      g_q);
    cudaGetSymbolAddress((void**)&k,      g_k);
    cudaGetSymbolAddress((void**)&v,      g_v);
    cudaGetSymbolAddress((void**)&att,    g_att);
    cudaGetSymbolAddress((void**)&h,      g_h);
    cudaGetSymbolAddress((void**)&pooled, g_pooled);
    float* tmp2 = tmp + (size_t)SS * DD;

    embed_kernel<<<SS, 256>>>(ids, emb_tok, emb_pos, tmp);
    ln_kernel<<<SS, 256>>>(tmp, nullptr, nullptr, ln_e_g, ln_e_b, x);

    dim3 gQKV(18, 32);          // 576 blocks
    dim3 gDs(6, 32, 2);         // 384 blocks, split-K=2
    dim3 gF(24, 32);            // 768 blocks

    for (int l = 0; l < NLAYERS; l++) {
        size_t woff  = (size_t)l * DD * DD;
        size_t foff1 = (size_t)l * DD * FF;
        size_t foff2 = (size_t)l * FF * DD;

        qkv_kernel<<<gQKV, 128>>>(x, wq + woff, wk + woff, wv + woff,
                                  bq + l * DD, bk + l * DD, bv + l * DD, q, k, v);

        attn_kernel<<<dim3(SS, HH), 128>>>(q, k, v, att);

        gemm_kernel<0><<<gDs, 128>>>(att, wo + woff, bo + l * DD, tmp, SS, DD, DD, 384);
        ln_kernel<<<SS, 256>>>(tmp, tmp2, x, ln1_g + l * DD, ln1_b + l * DD, x);

        gemm_kernel<2><<<gF, 128>>>(x, w1 + foff1, b1 + l * FF, h, SS, FF, DD, DD);
        gemm_kernel<0><<<gDs, 128>>>(h, w2m + foff2, b2 + l * DD, tmp, SS, DD, FF, 1536);
        ln_kernel<<<SS, 256>>>(tmp, tmp2, x, ln2_g + l * DD, ln2_b + l * DD, x);
    }

    pool_kernel<<<DD, 256>>>(x, pooled);
    final_kernel<<<1, 256>>>(pooled, fc_w, fc_b, (float*)d_out);
}

// round 4
// speedup vs baseline: 2.0724x; 1.6170x over previous
#include <cuda_runtime.h>
#include <math.h>

#define SS 2048
#define DD 768
#define HH 12
#define DHH 64
#define FF 3072
#define GG 16
#define W2W 256
#define NLAYERS 2

// ---------------- scratch (static device globals; no allocation) ----------------
__device__ float g_x[SS * DD];
__device__ float g_tmp[2 * SS * DD];   // holds split-K partials [part0 | part1]
__device__ float g_q[SS * DD];
__device__ float g_k[SS * DD];
__device__ float g_v[SS * DD];
__device__ float g_att[SS * DD];
__device__ float g_h[SS * FF];
__device__ float g_pooled[DD];

// ---------------- embedding ----------------
__global__ void embed_kernel(const int* __restrict__ ids,
                             const float* __restrict__ tok,
                             const float* __restrict__ pos,
                             float* __restrict__ out) {
    int s = blockIdx.x;
    int id = ids[s];
    const float* trow = tok + (size_t)id * DD;
    const float* prow = pos + (size_t)s * DD;
    float* orow = out + (size_t)s * DD;
    for (int d = threadIdx.x; d < DD; d += blockDim.x)
        orow[d] = trow[d] + prow[d];
}

// ---------------- layernorm: out = LN(inp (+ inp2) (+ resid)) * g + b ----------------
__global__ void ln_kernel(const float* __restrict__ inp,
                          const float* __restrict__ inp2,
                          const float* __restrict__ resid,
                          const float* __restrict__ gw,
                          const float* __restrict__ bw,
                          float* __restrict__ out) {
    int s = blockIdx.x;
    int tid = threadIdx.x;
    __shared__ float red[256];

    float vloc[3];
    float sum = 0.0f;
#pragma unroll
    for (int i = 0; i < 3; i++) {
        int d = tid + i * 256;
        float val = inp[(size_t)s * DD + d];
        if (inp2)  val += inp2[(size_t)s * DD + d];
        if (resid) val += resid[(size_t)s * DD + d];
        vloc[i] = val;
        sum += val;
    }
    red[tid] = sum;
    __syncthreads();
    for (int st = 128; st > 0; st >>= 1) {
        if (tid < st) red[tid] += red[tid + st];
        __syncthreads();
    }
    float mean = red[0] * (1.0f / DD);
    __syncthreads();

    float vs = 0.0f;
#pragma unroll
    for (int i = 0; i < 3; i++) {
        float dd = vloc[i] - mean;
        vs += dd * dd;
    }
    red[tid] = vs;
    __syncthreads();
    for (int st = 128; st > 0; st >>= 1) {
        if (tid < st) red[tid] += red[tid + st];
        __syncthreads();
    }
    float rstd = rsqrtf(red[0] * (1.0f / DD) + 1e-5f);

#pragma unroll
    for (int i = 0; i < 3; i++) {
        int d = tid + i * 256;
        out[(size_t)s * DD + d] = (vloc[i] - mean) * rstd * gw[d] + bw[d];
    }
}

// ---------------- GEMM core: 64x128 tile, 8x8 micro, register-staged prefetch ----------------
#define BM 64
#define BN 128
#define BK 16
#define BMP (BM + 4)

#define GEMM_BODY(Aptr, Bptr, Kld, Nld, kStart, kEnd)                                   \
    {                                                                                   \
        int k0p = (kStart);                                                             \
        _Pragma("unroll")                                                               \
        for (int j = 0; j < 2; j++) {                                                   \
            int idx = tid + j * 128; int r = idx >> 2; int c = (idx & 3) * 4;           \
            pa[j] = *(const float4*)&(Aptr)[(size_t)(bm + r) * (Kld) + k0p + c];        \
        }                                                                               \
        _Pragma("unroll")                                                               \
        for (int j = 0; j < 4; j++) {                                                   \
            int idx = tid + j * 128; int r = idx >> 5; int c = (idx & 31) * 4;          \
            pb[j] = *(const float4*)&(Bptr)[(size_t)(k0p + r) * (Nld) + bn + c];        \
        }                                                                               \
    }                                                                                   \
    for (int k0 = (kStart); k0 < (kEnd); k0 += BK) {                                    \
        _Pragma("unroll")                                                               \
        for (int j = 0; j < 2; j++) {                                                   \
            int idx = tid + j * 128; int r = idx >> 2; int c = (idx & 3) * 4;           \
            As[c + 0][r] = pa[j].x; As[c + 1][r] = pa[j].y;                             \
            As[c + 2][r] = pa[j].z; As[c + 3][r] = pa[j].w;                             \
        }                                                                               \
        _Pragma("unroll")                                                               \
        for (int j = 0; j < 4; j++) {                                                   \
            int idx = tid + j * 128; int r = idx >> 5; int c = (idx & 31) * 4;          \
            *(float4*)&Bs[r][c] = pb[j];                                                \
        }                                                                               \
        __syncthreads();                                                                \
        int kn = k0 + BK;                                                               \
        if (kn < (kEnd)) {                                                              \
            _Pragma("unroll")                                                           \
            for (int j = 0; j < 2; j++) {                                               \
                int idx = tid + j * 128; int r = idx >> 2; int c = (idx & 3) * 4;       \
                pa[j] = *(const float4*)&(Aptr)[(size_t)(bm + r) * (Kld) + kn + c];     \
            }                                                                           \
            _Pragma("unroll")                                                           \
            for (int j = 0; j < 4; j++) {                                               \
                int idx = tid + j * 128; int r = idx >> 5; int c = (idx & 31) * 4;      \
                pb[j] = *(const float4*)&(Bptr)[(size_t)(kn + r) * (Nld) + bn + c];     \
            }                                                                           \
        }                                                                               \
        _Pragma("unroll")                                                               \
        for (int kk = 0; kk < BK; kk++) {                                               \
            float a[8], b[8];                                                           \
            *(float4*)&a[0] = *(const float4*)&As[kk][tm];                              \
            *(float4*)&a[4] = *(const float4*)&As[kk][tm + 4];                          \
            *(float4*)&b[0] = *(const float4*)&Bs[kk][tn];                              \
            *(float4*)&b[4] = *(const float4*)&Bs[kk][tn + 4];                          \
            _Pragma("unroll")                                                           \
            for (int i = 0; i < 8; i++)                                                 \
                _Pragma("unroll")                                                       \
                for (int j = 0; j < 8; j++)                                             \
                    acc[i][j] = fmaf(a[i], b[j], acc[i][j]);                            \
        }                                                                               \
        __syncthreads();                                                                \
    }

template <int EPI>
__global__ void __launch_bounds__(128)
gemm_kernel(const float* __restrict__ A, const float* __restrict__ B,
            const float* __restrict__ bias, float* __restrict__ C,
            int M, int N, int K, int ksplit) {
    __shared__ float As[BK][BMP];
    __shared__ float Bs[BK][BN];

    int tid = threadIdx.x;
    int bm = blockIdx.y * BM;
    int bn = blockIdx.x * BN;
    int z = blockIdx.z;
    int kStart = z * ksplit;
    int kEnd = min(K, kStart + ksplit);
    C += (size_t)z * M * N;

    int ty = tid >> 4, tx = tid & 15;
    int tm = ty * 8, tn = tx * 8;
    float acc[8][8] = {};
    float4 pa[2], pb[4];

    GEMM_BODY(A, B, K, N, kStart, kEnd)

    float bb[8] = {};
    if (z == 0) {
        *(float4*)&bb[0] = *(const float4*)&bias[bn + tn];
        *(float4*)&bb[4] = *(const float4*)&bias[bn + tn + 4];
    }

#pragma unroll
    for (int i = 0; i < 8; i++) {
        float o[8];
#pragma unroll
        for (int j = 0; j < 8; j++) {
            float val = acc[i][j] + bb[j];
            if (EPI == 2) {
                float x3 = val * val * val;
                val = 0.5f * val * (1.0f + tanhf(0.7978845608028654f * (val + 0.044715f * x3)));
            }
            o[j] = val;
        }
        float* crow = &C[(size_t)(bm + tm + i) * N + bn + tn];
        *(float4*)&crow[0] = *(float4*)&o[0];
        *(float4*)&crow[4] = *(float4*)&o[4];
    }
}

// Fused QKV projection
__global__ void __launch_bounds__(128)
qkv_kernel(const float* __restrict__ X,
           const float* __restrict__ Wq, const float* __restrict__ Wk, const float* __restrict__ Wv,
           const float* __restrict__ Bq, const float* __restrict__ Bk, const float* __restrict__ Bv,
           float* __restrict__ Q, float* __restrict__ Ko, float* __restrict__ V) {
    __shared__ float As[BK][BMP];
    __shared__ float Bs[BK][BN];

    int tid = threadIdx.x;
    int bm = blockIdx.y * BM;
    int which = blockIdx.x / 6;
    int bn = (blockIdx.x % 6) * BN;

    const float* B   = (which == 0) ? Wq : (which == 1) ? Wk : Wv;
    const float* bia = (which == 0) ? Bq : (which == 1) ? Bk : Bv;
    float*       C   = (which == 0) ? Q  : (which == 1) ? Ko : V;
    float scale = (which == 0) ? 0.125f : 1.0f;

    int ty = tid >> 4, tx = tid & 15;
    int tm = ty * 8, tn = tx * 8;
    float acc[8][8] = {};
    float4 pa[2], pb[4];

    GEMM_BODY(X, B, DD, DD, 0, DD)

    float bb[8];
    *(float4*)&bb[0] = *(const float4*)&bia[bn + tn];
    *(float4*)&bb[4] = *(const float4*)&bia[bn + tn + 4];

#pragma unroll
    for (int i = 0; i < 8; i++) {
        float o[8];
#pragma unroll
        for (int j = 0; j < 8; j++)
            o[j] = (acc[i][j] + bb[j]) * scale;
        float* crow = &C[(size_t)(bm + tm + i) * DD + bn + tn];
        *(float4*)&crow[0] = *(float4*)&o[0];
        *(float4*)&crow[4] = *(float4*)&o[4];
    }
}

// ---------------- tiled local+global attention (flash-style) ----------------
// One block per (64-query tile, head). Keys enumerated as kk(i) = i<16 ? i : lo-16+i,
// lo = max(16, q0-256); i>=16 keys masked by |kk - s| <= 256. Rows s<16 skipped
// (written by attn_full below).
#define AP 68   // padded row stride (floats)

__global__ void __launch_bounds__(128)
attn_tiled(const float* __restrict__ q, const float* __restrict__ k,
           const float* __restrict__ v, float* __restrict__ out) {
    extern __shared__ float smem[];
    float (*Qs)[AP] = (float(*)[AP])smem;               // [d][q]
    float (*KP)[AP] = (float(*)[AP])(smem + 64 * AP);   // Ks: [d][k]  ->  Ps: [k][q]
    float (*Vs)[AP] = (float(*)[AP])(smem + 2 * 64 * AP); // [k][d]

    int tid = threadIdx.x;
    int h = blockIdx.y;
    int q0 = blockIdx.x * 64;
    int ty = tid >> 3;   // 0..15 (query dim, 4 rows each)
    int tx = tid & 7;    // 0..7  (key/dim cols, 8 each)

    int lo = max(GG, q0 - W2W);
    int hi = min(SS - 1, q0 + 63 + W2W);
    int nk = GG + (hi - lo + 1);
    int ntiles = (nk + 63) >> 6;

    // load Q tile transposed: Qs[d][ql]
#pragma unroll
    for (int j4 = 0; j4 < 8; j4++) {
        int lin = tid + j4 * 128;
        int ql = lin >> 4;
        int dp = (lin & 15) * 4;
        float4 qv = *(const float4*)&q[(size_t)(q0 + ql) * DD + h * DHH + dp];
        Qs[dp + 0][ql] = qv.x; Qs[dp + 1][ql] = qv.y;
        Qs[dp + 2][ql] = qv.z; Qs[dp + 3][ql] = qv.w;
    }

    float m[4], l[4], O[4][8];
#pragma unroll
    for (int i = 0; i < 4; i++) { m[i] = -1e30f; l[i] = 0.0f; }
#pragma unroll
    for (int i = 0; i < 4; i++)
#pragma unroll
        for (int j = 0; j < 8; j++) O[i][j] = 0.0f;

    for (int t = 0; t < ntiles; t++) {
        int ibase = t * 64;
        // load K tile (transposed -> KP[d][kl]) and V tile (natural -> Vs[kl][d])
#pragma unroll
        for (int j4 = 0; j4 < 8; j4++) {
            int lin = tid + j4 * 128;
            int kl = lin >> 4;
            int dp = (lin & 15) * 4;
            int i = ibase + kl;
            float4 kv = make_float4(0.f, 0.f, 0.f, 0.f);
            float4 vv = make_float4(0.f, 0.f, 0.f, 0.f);
            if (i < nk) {
                int kk = (i < GG) ? i : lo - GG + i;
                kv = *(const float4*)&k[(size_t)kk * DD + h * DHH + dp];
                vv = *(const float4*)&v[(size_t)kk * DD + h * DHH + dp];
            }
            KP[dp + 0][kl] = kv.x; KP[dp + 1][kl] = kv.y;
            KP[dp + 2][kl] = kv.z; KP[dp + 3][kl] = kv.w;
            *(float4*)&Vs[kl][dp] = vv;
        }
        __syncthreads();

        // S = Q·K^T  (4x8 micro-tile per thread)
        float sacc[4][8] = {};
#pragma unroll
        for (int d = 0; d < 64; d++) {
            float a[4], b[8];
            *(float4*)&a[0] = *(const float4*)&Qs[d][ty * 4];
            *(float4*)&b[0] = *(const float4*)&KP[d][tx * 8];
            *(float4*)&b[4] = *(const float4*)&KP[d][tx * 8 + 4];
#pragma unroll
            for (int i = 0; i < 4; i++)
#pragma unroll
                for (int j = 0; j < 8; j++)
                    sacc[i][j] = fmaf(a[i], b[j], sacc[i][j]);
        }
        __syncthreads();   // done reading KP as K; safe to overwrite with P

        // mask + online softmax
#pragma unroll
        for (int i = 0; i < 4; i++) {
            int s = q0 + ty * 4 + i;
#pragma unroll
            for (int j = 0; j < 8; j++) {
                int idx = ibase + tx * 8 + j;
                int kk = (idx < GG) ? idx : lo - GG + idx;
                int dk = kk - s;
                bool valid = (idx < nk) && ((idx < GG) || (dk <= W2W && dk >= -W2W));
                if (!valid) sacc[i][j] = -1e30f;
            }
            float rmax = sacc[i][0];
#pragma unroll
            for (int j = 1; j < 8; j++) rmax = fmaxf(rmax, sacc[i][j]);
#pragma unroll
            for (int o = 1; o < 8; o <<= 1)
                rmax = fmaxf(rmax, __shfl_xor_sync(0xffffffff, rmax, o));
            float mn = fmaxf(m[i], rmax);
            float fac = __expf(m[i] - mn);
            float rsum = 0.0f;
#pragma unroll
            for (int j = 0; j < 8; j++) {
                float p = __expf(sacc[i][j] - mn);
                sacc[i][j] = p;
                rsum += p;
            }
#pragma unroll
            for (int o = 1; o < 8; o <<= 1)
                rsum += __shfl_xor_sync(0xffffffff, rsum, o);
            l[i] = l[i] * fac + rsum;
            m[i] = mn;
#pragma unroll
            for (int j = 0; j < 8; j++) O[i][j] *= fac;
        }

        // write P transposed: KP[kl][q]
#pragma unroll
        for (int j = 0; j < 8; j++)
#pragma unroll
            for (int i = 0; i < 4; i++)
                KP[tx * 8 + j][ty * 4 + i] = sacc[i][j];
        __syncthreads();

        // O += P·V
#pragma unroll
        for (int kl = 0; kl < 64; kl++) {
            float a[4], b[8];
            *(float4*)&a[0] = *(const float4*)&KP[kl][ty * 4];
            *(float4*)&b[0] = *(const float4*)&Vs[kl][tx * 8];
            *(float4*)&b[4] = *(const float4*)&Vs[kl][tx * 8 + 4];
#pragma unroll
            for (int i = 0; i < 4; i++)
#pragma unroll
                for (int j = 0; j < 8; j++)
                    O[i][j] = fmaf(a[i], b[j], O[i][j]);
        }
        __syncthreads();
    }

    // normalize + store (skip global query rows; attn_full writes them)
#pragma unroll
    for (int i = 0; i < 4; i++) {
        int s = q0 + ty * 4 + i;
        if (s < GG) continue;
        float inv = 1.0f / l[i];
        float o[8];
#pragma unroll
        for (int j = 0; j < 8; j++) o[j] = O[i][j] * inv;
        float* orow = &out[(size_t)s * DD + h * DHH + tx * 8];
        *(float4*)&orow[0] = *(float4*)&o[0];
        *(float4*)&orow[4] = *(float4*)&o[4];
    }
}

// ---------------- full attention for global queries (s < G): one block per (s,h) ----------------
__global__ void __launch_bounds__(128)
attn_full(const float* __restrict__ q, const float* __restrict__ k,
          const float* __restrict__ v, float* __restrict__ out) {
    int s = blockIdx.x;      // 0..15
    int h = blockIdx.y;
    int tid = threadIdx.x;

    __shared__ float sc[SS];
    __shared__ float qs[DHH];
    __shared__ float red[128];
    __shared__ float pacc[2][DHH];

    if (tid < DHH) qs[tid] = q[(size_t)s * DD + h * DHH + tid];
    __syncthreads();

    for (int i = tid; i < SS; i += 128) {
        const float4* kr = (const float4*)(k + (size_t)i * DD + h * DHH);
        float dot = 0.0f;
#pragma unroll
        for (int d4 = 0; d4 < 16; d4++) {
            float4 kv = kr[d4];
            dot += qs[4 * d4 + 0] * kv.x + qs[4 * d4 + 1] * kv.y +
                   qs[4 * d4 + 2] * kv.z + qs[4 * d4 + 3] * kv.w;
        }
        sc[i] = dot;
    }
    __syncthreads();

    float mx = -1e30f;
    for (int i = tid; i < SS; i += 128) mx = fmaxf(mx, sc[i]);
    red[tid] = mx;
    __syncthreads();
    for (int st = 64; st > 0; st >>= 1) {
        if (tid < st) red[tid] = fmaxf(red[tid], red[tid + st]);
        __syncthreads();
    }
    mx = red[0];
    __syncthreads();

    float ssum = 0.0f;
    for (int i = tid; i < SS; i += 128) {
        float p = __expf(sc[i] - mx);
        sc[i] = p;
        ssum += p;
    }
    red[tid] = ssum;
    __syncthreads();
    for (int st = 64; st > 0; st >>= 1) {
        if (tid < st) red[tid] += red[tid + st];
        __syncthreads();
    }
    float inv = 1.0f / red[0];
    __syncthreads();

    int d = tid & 63;
    int half = tid >> 6;
    float acc = 0.0f;
    for (int i = half; i < SS; i += 2)
        acc = fmaf(sc[i], v[(size_t)i * DD + h * DHH + d], acc);
    pacc[half][d] = acc;
    __syncthreads();
    if (tid < DHH)
        out[(size_t)s * DD + h * DHH + tid] = (pacc[0][tid] + pacc[1][tid]) * inv;
}

// ---------------- pooling + classifier ----------------
__global__ void pool_kernel(const float* __restrict__ x, float* __restrict__ pooled) {
    int d = blockIdx.x;
    int tid = threadIdx.x;
    __shared__ float red[256];
    float sum = 0.0f;
    for (int s = tid; s < SS; s += 256) sum += x[(size_t)s * DD + d];
    red[tid] = sum;
    __syncthreads();
    for (int st = 128; st > 0; st >>= 1) {
        if (tid < st) red[tid] += red[tid + st];
        __syncthreads();
    }
    if (tid == 0) pooled[d] = red[0] * (1.0f / SS);
}

__global__ void final_kernel(const float* __restrict__ pooled,
                             const float* __restrict__ w,
                             const float* __restrict__ b,
                             float* __restrict__ out) {
    int tid = threadIdx.x;
    __shared__ float red[256];
    float sum = 0.0f;
    for (int d = tid; d < DD; d += 256) sum += pooled[d] * w[d];
    red[tid] = sum;
    __syncthreads();
    for (int st = 128; st > 0; st >>= 1) {
        if (tid < st) red[tid] += red[tid + st];
        __syncthreads();
    }
    if (tid == 0) out[0] = red[0] + b[0];
}

// ---------------- launch ----------------
extern "C" void kernel_launch(void* const* d_in, const int* in_sizes, int n_in,
                              void* d_out, int out_size) {
    const int*   ids     = (const int*)d_in[0];
    const float* emb_tok = (const float*)d_in[2];
    const float* emb_pos = (const float*)d_in[3];
    const float* ln_e_g  = (const float*)d_in[4];
    const float* ln_e_b  = (const float*)d_in[5];
    const float* wq      = (const float*)d_in[6];
    const float* bq      = (const float*)d_in[7];
    const float* wk      = (const float*)d_in[8];
    const float* bk      = (const float*)d_in[9];
    const float* wv      = (const float*)d_in[10];
    const float* bv      = (const float*)d_in[11];
    const float* wo      = (const float*)d_in[12];
    const float* bo      = (const float*)d_in[13];
    const float* ln1_g   = (const float*)d_in[14];
    const float* ln1_b   = (const float*)d_in[15];
    const float* w1      = (const float*)d_in[16];
    const float* b1      = (const float*)d_in[17];
    const float* w2m     = (const float*)d_in[18];
    const float* b2      = (const float*)d_in[19];
    const float* ln2_g   = (const float*)d_in[20];
    const float* ln2_b   = (const float*)d_in[21];
    const float* fc_w    = (const float*)d_in[22];
    const float* fc_b    = (const float*)d_in[23];

    float *x, *tmp, *q, *k, *v, *att, *h, *pooled;
    cudaGetSymbolAddress((void**)&x,      g_x);
    cudaGetSymbolAddress((void**)&tmp,    g_tmp);
    cudaGetSymbolAddress((void**)&q,      g_q);
    cudaGetSymbolAddress((void**)&k,      g_k);
    cudaGetSymbolAddress((void**)&v,      g_v);
    cudaGetSymbolAddress((void**)&att,    g_att);
    cudaGetSymbolAddress((void**)&h,      g_h);
    cudaGetSymbolAddress((void**)&pooled, g_pooled);
    float* tmp2 = tmp + (size_t)SS * DD;

    const int ASMEM = 3 * 64 * AP * sizeof(float);   // ~52 KB
    cudaFuncSetAttribute(attn_tiled, cudaFuncAttributeMaxDynamicSharedMemorySize, ASMEM);

    embed_kernel<<<SS, 256>>>(ids, emb_tok, emb_pos, tmp);
    ln_kernel<<<SS, 256>>>(tmp, nullptr, nullptr, ln_e_g, ln_e_b, x);

    dim3 gQKV(18, 32);          // 576 blocks
    dim3 gDs(6, 32, 2);         // 384 blocks, split-K=2
    dim3 gF(24, 32);            // 768 blocks

    for (int l = 0; l < NLAYERS; l++) {
        size_t woff  = (size_t)l * DD * DD;
        size_t foff1 = (size_t)l * DD * FF;
        size_t foff2 = (size_t)l * FF * DD;

        qkv_kernel<<<gQKV, 128>>>(x, wq + woff, wk + woff, wv + woff,
                                  bq + l * DD, bk + l * DD, bv + l * DD, q, k, v);

        attn_tiled<<<dim3(SS / 64, HH), 128, ASMEM>>>(q, k, v, att);
        attn_full<<<dim3(GG, HH), 128>>>(q, k, v, att);

        gemm_kernel<0><<<gDs, 128>>>(att, wo + woff, bo + l * DD, tmp, SS, DD, DD, 384);
        ln_kernel<<<SS, 256>>>(tmp, tmp2, x, ln1_g + l * DD, ln1_b + l * DD, x);

        gemm_kernel<2><<<gF, 128>>>(x, w1 + foff1, b1 + l * FF, h, SS, FF, DD, DD);
        gemm_kernel<0><<<gDs, 128>>>(h, w2m + foff2, b2 + l * DD, tmp, SS, DD, FF, 1536);
        ln_kernel<<<SS, 256>>>(tmp, tmp2, x, ln2_g + l * DD, ln2_b + l * DD, x);
    }

    pool_kernel<<<DD, 256>>>(x, pooled);
    final_kernel<<<1, 256>>>(pooled, fc_w, fc_b, (float*)d_out);
}

// round 5
// speedup vs baseline: 3.4019x; 1.6415x over previous
#include <cuda_runtime.h>
#include <math.h>
#include <stdint.h>

#define SS 2048
#define DD 768
#define HH 12
#define DHH 64
#define FF 3072
#define GG 16
#define W2W 256
#define NLAYERS 2

// ---------------- scratch (static device globals; no allocation) ----------------
__device__ float g_x[SS * DD];
__device__ float g_tmp[2 * SS * DD];   // split-K partials [part0 | part1]
__device__ float g_q[SS * DD];
__device__ float g_k[SS * DD];
__device__ float g_v[SS * DD];
__device__ float g_att[SS * DD];
__device__ float g_h[SS * FF];
__device__ float g_pooled[DD];

// ---------------- embedding ----------------
__global__ void embed_kernel(const int* __restrict__ ids,
                             const float* __restrict__ tok,
                             const float* __restrict__ pos,
                             float* __restrict__ out) {
    int s = blockIdx.x;
    int id = ids[s];
    const float* trow = tok + (size_t)id * DD;
    const float* prow = pos + (size_t)s * DD;
    float* orow = out + (size_t)s * DD;
    for (int d = threadIdx.x; d < DD; d += blockDim.x)
        orow[d] = trow[d] + prow[d];
}

// ---------------- layernorm: out = LN(inp (+ inp2) (+ resid)) * g + b ----------------
__global__ void ln_kernel(const float* __restrict__ inp,
                          const float* __restrict__ inp2,
                          const float* __restrict__ resid,
                          const float* __restrict__ gw,
                          const float* __restrict__ bw,
                          float* __restrict__ out) {
    int s = blockIdx.x;
    int tid = threadIdx.x;
    __shared__ float red[256];

    float vloc[3];
    float sum = 0.0f;
#pragma unroll
    for (int i = 0; i < 3; i++) {
        int d = tid + i * 256;
        float val = inp[(size_t)s * DD + d];
        if (inp2)  val += inp2[(size_t)s * DD + d];
        if (resid) val += resid[(size_t)s * DD + d];
        vloc[i] = val;
        sum += val;
    }
    red[tid] = sum;
    __syncthreads();
    for (int st = 128; st > 0; st >>= 1) {
        if (tid < st) red[tid] += red[tid + st];
        __syncthreads();
    }
    float mean = red[0] * (1.0f / DD);
    __syncthreads();

    float vs = 0.0f;
#pragma unroll
    for (int i = 0; i < 3; i++) {
        float dd = vloc[i] - mean;
        vs += dd * dd;
    }
    red[tid] = vs;
    __syncthreads();
    for (int st = 128; st > 0; st >>= 1) {
        if (tid < st) red[tid] += red[tid + st];
        __syncthreads();
    }
    float rstd = rsqrtf(red[0] * (1.0f / DD) + 1e-5f);

#pragma unroll
    for (int i = 0; i < 3; i++) {
        int d = tid + i * 256;
        out[(size_t)s * DD + d] = (vloc[i] - mean) * rstd * gw[d] + bw[d];
    }
}

// ================= TF32 tensor-core GEMM =================
// Block tile 128x128, BK=16, 256 threads = 8 warps (4 m x 2 n), warp tile 32x64.
// mma.sync.aligned.m16n8k8.row.col.f32.tf32.tf32.f32
#define TBM 128
#define TBN 128
#define TBK 16
#define TST 136   // smem row stride: 136 % 32 == 8 -> conflict-free fragment loads

__device__ __forceinline__ uint32_t f2tf32(float x) {
    uint32_t t;
    asm("cvt.rna.tf32.f32 %0, %1;" : "=r"(t) : "f"(x));
    return t;
}

__device__ __forceinline__ void mma_tf32(float* c,
                                         uint32_t a0, uint32_t a1, uint32_t a2, uint32_t a3,
                                         uint32_t b0, uint32_t b1) {
    asm volatile(
        "mma.sync.aligned.m16n8k8.row.col.f32.tf32.tf32.f32 "
        "{%0,%1,%2,%3}, {%4,%5,%6,%7}, {%8,%9}, {%0,%1,%2,%3};"
        : "+f"(c[0]), "+f"(c[1]), "+f"(c[2]), "+f"(c[3])
        : "r"(a0), "r"(a1), "r"(a2), "r"(a3), "r"(b0), "r"(b1));
}

// Mainloop: acc[2][8][4] += A[bm:bm+128, kStart:kEnd] @ B[kStart:kEnd, bn:bn+128]
__device__ __forceinline__ void tf32_mainloop(
    const float* __restrict__ A, const float* __restrict__ B,
    int K, int N, int bm, int bn, int kStart, int kEnd,
    uint32_t (*As)[TST], uint32_t (*Bs)[TST], float acc[2][8][4]) {

    int tid = threadIdx.x;
    int lane = tid & 31;
    int wid = tid >> 5;
    int wm = wid >> 1;          // 0..3
    int wn = wid & 1;           // 0..1
    int grp = lane >> 2;        // 0..7
    int tig = lane & 3;         // 0..3

    int ra = tid >> 1,  ca = (tid & 1) * 8;    // A: row 0..127, col group {0,8}
    int rb = tid >> 4,  cb = (tid & 15) * 8;   // B: row 0..15,  col group 0..120

    float4 pa0, pa1, pb0, pb1;
    pa0 = *(const float4*)&A[(size_t)(bm + ra) * K + kStart + ca];
    pa1 = *(const float4*)&A[(size_t)(bm + ra) * K + kStart + ca + 4];
    pb0 = *(const float4*)&B[(size_t)(kStart + rb) * N + bn + cb];
    pb1 = *(const float4*)&B[(size_t)(kStart + rb) * N + bn + cb + 4];

    for (int k0 = kStart; k0 < kEnd; k0 += TBK) {
        // store A transposed (tf32): As[k][m]
        As[ca + 0][ra] = f2tf32(pa0.x);
        As[ca + 1][ra] = f2tf32(pa0.y);
        As[ca + 2][ra] = f2tf32(pa0.z);
        As[ca + 3][ra] = f2tf32(pa0.w);
        As[ca + 4][ra] = f2tf32(pa1.x);
        As[ca + 5][ra] = f2tf32(pa1.y);
        As[ca + 6][ra] = f2tf32(pa1.z);
        As[ca + 7][ra] = f2tf32(pa1.w);
        // store B direct (tf32): Bs[k][n]
        Bs[rb][cb + 0] = f2tf32(pb0.x);
        Bs[rb][cb + 1] = f2tf32(pb0.y);
        Bs[rb][cb + 2] = f2tf32(pb0.z);
        Bs[rb][cb + 3] = f2tf32(pb0.w);
        Bs[rb][cb + 4] = f2tf32(pb1.x);
        Bs[rb][cb + 5] = f2tf32(pb1.y);
        Bs[rb][cb + 6] = f2tf32(pb1.z);
        Bs[rb][cb + 7] = f2tf32(pb1.w);
        __syncthreads();

        int kn = k0 + TBK;
        if (kn < kEnd) {
            pa0 = *(const float4*)&A[(size_t)(bm + ra) * K + kn + ca];
            pa1 = *(const float4*)&A[(size_t)(bm + ra) * K + kn + ca + 4];
            pb0 = *(const float4*)&B[(size_t)(kn + rb) * N + bn + cb];
            pb1 = *(const float4*)&B[(size_t)(kn + rb) * N + bn + cb + 4];
        }

#pragma unroll
        for (int ks = 0; ks < 2; ks++) {
            int kb = ks * 8;
            uint32_t af[2][4];
#pragma unroll
            for (int mi = 0; mi < 2; mi++) {
                int m = wm * 32 + mi * 16 + grp;
                af[mi][0] = As[kb + tig][m];
                af[mi][1] = As[kb + tig][m + 8];
                af[mi][2] = As[kb + tig + 4][m];
                af[mi][3] = As[kb + tig + 4][m + 8];
            }
            uint32_t bf[8][2];
#pragma unroll
            for (int ni = 0; ni < 8; ni++) {
                int n = wn * 64 + ni * 8 + grp;
                bf[ni][0] = Bs[kb + tig][n];
                bf[ni][1] = Bs[kb + tig + 4][n];
            }
#pragma unroll
            for (int mi = 0; mi < 2; mi++)
#pragma unroll
                for (int ni = 0; ni < 8; ni++)
                    mma_tf32(acc[mi][ni], af[mi][0], af[mi][1], af[mi][2], af[mi][3],
                             bf[ni][0], bf[ni][1]);
        }
        __syncthreads();
    }
}

__device__ __forceinline__ float gelu_f(float v) {
    float x3 = v * v * v;
    return 0.5f * v * (1.0f + tanhf(0.7978845608028654f * (v + 0.044715f * x3)));
}

// EPI: 0 = +bias, 2 = gelu(+bias). split-K via blockIdx.z (z>0: no bias, write partial).
template <int EPI>
__global__ void __launch_bounds__(256)
gemm_tf32(const float* __restrict__ A, const float* __restrict__ B,
          const float* __restrict__ bias, float* __restrict__ C,
          int M, int N, int K, int ksplit) {
    __shared__ uint32_t As[TBK][TST];
    __shared__ uint32_t Bs[TBK][TST];

    int bm = blockIdx.y * TBM;
    int bn = blockIdx.x * TBN;
    int z = blockIdx.z;
    int kStart = z * ksplit;
    int kEnd = min(K, kStart + ksplit);
    C += (size_t)z * M * N;

    float acc[2][8][4];
#pragma unroll
    for (int mi = 0; mi < 2; mi++)
#pragma unroll
        for (int ni = 0; ni < 8; ni++)
#pragma unroll
            for (int c = 0; c < 4; c++) acc[mi][ni][c] = 0.0f;

    tf32_mainloop(A, B, K, N, bm, bn, kStart, kEnd, As, Bs, acc);

    int lane = threadIdx.x & 31;
    int wid = threadIdx.x >> 5;
    int wm = wid >> 1, wn = wid & 1;
    int grp = lane >> 2, tig = lane & 3;

#pragma unroll
    for (int mi = 0; mi < 2; mi++) {
        int row = bm + wm * 32 + mi * 16 + grp;
#pragma unroll
        for (int ni = 0; ni < 8; ni++) {
            int col = bn + wn * 64 + ni * 8 + tig * 2;
            float b0 = 0.0f, b1 = 0.0f;
            if (z == 0) { b0 = bias[col]; b1 = bias[col + 1]; }
            float v0 = acc[mi][ni][0] + b0;
            float v1 = acc[mi][ni][1] + b1;
            float v2 = acc[mi][ni][2] + b0;
            float v3 = acc[mi][ni][3] + b1;
            if (EPI == 2) { v0 = gelu_f(v0); v1 = gelu_f(v1); v2 = gelu_f(v2); v3 = gelu_f(v3); }
            *(float2*)&C[(size_t)row * N + col]       = make_float2(v0, v1);
            *(float2*)&C[(size_t)(row + 8) * N + col] = make_float2(v2, v3);
        }
    }
}

// Fused QKV: grid.x = 18; tiles [0,6)->Q (scaled 0.125), [6,12)->K, [12,18)->V.
__global__ void __launch_bounds__(256)
qkv_tf32(const float* __restrict__ X,
         const float* __restrict__ Wq, const float* __restrict__ Wk, const float* __restrict__ Wv,
         const float* __restrict__ Bq, const float* __restrict__ Bk, const float* __restrict__ Bv,
         float* __restrict__ Q, float* __restrict__ Ko, float* __restrict__ V) {
    __shared__ uint32_t As[TBK][TST];
    __shared__ uint32_t Bs[TBK][TST];

    int bm = blockIdx.y * TBM;
    int which = blockIdx.x / 6;
    int bn = (blockIdx.x % 6) * TBN;

    const float* B   = (which == 0) ? Wq : (which == 1) ? Wk : Wv;
    const float* bia = (which == 0) ? Bq : (which == 1) ? Bk : Bv;
    float*       C   = (which == 0) ? Q  : (which == 1) ? Ko : V;
    float scale = (which == 0) ? 0.125f : 1.0f;

    float acc[2][8][4];
#pragma unroll
    for (int mi = 0; mi < 2; mi++)
#pragma unroll
        for (int ni = 0; ni < 8; ni++)
#pragma unroll
            for (int c = 0; c < 4; c++) acc[mi][ni][c] = 0.0f;

    tf32_mainloop(X, B, DD, DD, bm, bn, 0, DD, As, Bs, acc);

    int lane = threadIdx.x & 31;
    int wid = threadIdx.x >> 5;
    int wm = wid >> 1, wn = wid & 1;
    int grp = lane >> 2, tig = lane & 3;

#pragma unroll
    for (int mi = 0; mi < 2; mi++) {
        int row = bm + wm * 32 + mi * 16 + grp;
#pragma unroll
        for (int ni = 0; ni < 8; ni++) {
            int col = bn + wn * 64 + ni * 8 + tig * 2;
            float b0 = bia[col], b1 = bia[col + 1];
            float v0 = (acc[mi][ni][0] + b0) * scale;
            float v1 = (acc[mi][ni][1] + b1) * scale;
            float v2 = (acc[mi][ni][2] + b0) * scale;
            float v3 = (acc[mi][ni][3] + b1) * scale;
            *(float2*)&C[(size_t)row * DD + col]       = make_float2(v0, v1);
            *(float2*)&C[(size_t)(row + 8) * DD + col] = make_float2(v2, v3);
        }
    }
}

// ---------------- tiled local+global attention (flash-style, fp32) ----------------
#define AP 68

__global__ void __launch_bounds__(128)
attn_tiled(const float* __restrict__ q, const float* __restrict__ k,
           const float* __restrict__ v, float* __restrict__ out) {
    extern __shared__ float smem[];
    float (*Qs)[AP] = (float(*)[AP])smem;
    float (*KP)[AP] = (float(*)[AP])(smem + 64 * AP);
    float (*Vs)[AP] = (float(*)[AP])(smem + 2 * 64 * AP);

    int tid = threadIdx.x;
    int h = blockIdx.y;
    int q0 = blockIdx.x * 64;
    int ty = tid >> 3;
    int tx = tid & 7;

    int lo = max(GG, q0 - W2W);
    int hi = min(SS - 1, q0 + 63 + W2W);
    int nk = GG + (hi - lo + 1);
    int ntiles = (nk + 63) >> 6;

#pragma unroll
    for (int j4 = 0; j4 < 8; j4++) {
        int lin = tid + j4 * 128;
        int ql = lin >> 4;
        int dp = (lin & 15) * 4;
        float4 qv = *(const float4*)&q[(size_t)(q0 + ql) * DD + h * DHH + dp];
        Qs[dp + 0][ql] = qv.x; Qs[dp + 1][ql] = qv.y;
        Qs[dp + 2][ql] = qv.z; Qs[dp + 3][ql] = qv.w;
    }

    float m[4], l[4], O[4][8];
#pragma unroll
    for (int i = 0; i < 4; i++) { m[i] = -1e30f; l[i] = 0.0f; }
#pragma unroll
    for (int i = 0; i < 4; i++)
#pragma unroll
        for (int j = 0; j < 8; j++) O[i][j] = 0.0f;

    for (int t = 0; t < ntiles; t++) {
        int ibase = t * 64;
#pragma unroll
        for (int j4 = 0; j4 < 8; j4++) {
            int lin = tid + j4 * 128;
            int kl = lin >> 4;
            int dp = (lin & 15) * 4;
            int i = ibase + kl;
            float4 kv = make_float4(0.f, 0.f, 0.f, 0.f);
            float4 vv = make_float4(0.f, 0.f, 0.f, 0.f);
            if (i < nk) {
                int kk = (i < GG) ? i : lo - GG + i;
                kv = *(const float4*)&k[(size_t)kk * DD + h * DHH + dp];
                vv = *(const float4*)&v[(size_t)kk * DD + h * DHH + dp];
            }
            KP[dp + 0][kl] = kv.x; KP[dp + 1][kl] = kv.y;
            KP[dp + 2][kl] = kv.z; KP[dp + 3][kl] = kv.w;
            *(float4*)&Vs[kl][dp] = vv;
        }
        __syncthreads();

        float sacc[4][8] = {};
#pragma unroll
        for (int d = 0; d < 64; d++) {
            float a[4], b[8];
            *(float4*)&a[0] = *(const float4*)&Qs[d][ty * 4];
            *(float4*)&b[0] = *(const float4*)&KP[d][tx * 8];
            *(float4*)&b[4] = *(const float4*)&KP[d][tx * 8 + 4];
#pragma unroll
            for (int i = 0; i < 4; i++)
#pragma unroll
                for (int j = 0; j < 8; j++)
                    sacc[i][j] = fmaf(a[i], b[j], sacc[i][j]);
        }
        __syncthreads();

#pragma unroll
        for (int i = 0; i < 4; i++) {
            int s = q0 + ty * 4 + i;
#pragma unroll
            for (int j = 0; j < 8; j++) {
                int idx = ibase + tx * 8 + j;
                int kk = (idx < GG) ? idx : lo - GG + idx;
                int dk = kk - s;
                bool valid = (idx < nk) && ((idx < GG) || (dk <= W2W && dk >= -W2W));
                if (!valid) sacc[i][j] = -1e30f;
            }
            float rmax = sacc[i][0];
#pragma unroll
            for (int j = 1; j < 8; j++) rmax = fmaxf(rmax, sacc[i][j]);
#pragma unroll
            for (int o = 1; o < 8; o <<= 1)
                rmax = fmaxf(rmax, __shfl_xor_sync(0xffffffff, rmax, o));
            float mn = fmaxf(m[i], rmax);
            float fac = __expf(m[i] - mn);
            float rsum = 0.0f;
#pragma unroll
            for (int j = 0; j < 8; j++) {
                float p = __expf(sacc[i][j] - mn);
                sacc[i][j] = p;
                rsum += p;
            }
#pragma unroll
            for (int o = 1; o < 8; o <<= 1)
                rsum += __shfl_xor_sync(0xffffffff, rsum, o);
            l[i] = l[i] * fac + rsum;
            m[i] = mn;
#pragma unroll
            for (int j = 0; j < 8; j++) O[i][j] *= fac;
        }

#pragma unroll
        for (int j = 0; j < 8; j++)
#pragma unroll
            for (int i = 0; i < 4; i++)
                KP[tx * 8 + j][ty * 4 + i] = sacc[i][j];
        __syncthreads();

#pragma unroll
        for (int kl = 0; kl < 64; kl++) {
            float a[4], b[8];
            *(float4*)&a[0] = *(const float4*)&KP[kl][ty * 4];
            *(float4*)&b[0] = *(const float4*)&Vs[kl][tx * 8];
            *(float4*)&b[4] = *(const float4*)&Vs[kl][tx * 8 + 4];
#pragma unroll
            for (int i = 0; i < 4; i++)
#pragma unroll
                for (int j = 0; j < 8; j++)
                    O[i][j] = fmaf(a[i], b[j], O[i][j]);
        }
        __syncthreads();
    }

#pragma unroll
    for (int i = 0; i < 4; i++) {
        int s = q0 + ty * 4 + i;
        if (s < GG) continue;
        float inv = 1.0f / l[i];
        float o[8];
#pragma unroll
        for (int j = 0; j < 8; j++) o[j] = O[i][j] * inv;
        float* orow = &out[(size_t)s * DD + h * DHH + tx * 8];
        *(float4*)&orow[0] = *(float4*)&o[0];
        *(float4*)&orow[4] = *(float4*)&o[4];
    }
}

// ---------------- full attention for global queries (s < G) ----------------
__global__ void __launch_bounds__(128)
attn_full(const float* __restrict__ q, const float* __restrict__ k,
          const float* __restrict__ v, float* __restrict__ out) {
    int s = blockIdx.x;
    int h = blockIdx.y;
    int tid = threadIdx.x;

    __shared__ float sc[SS];
    __shared__ float qs[DHH];
    __shared__ float red[128];
    __shared__ float pacc[2][DHH];

    if (tid < DHH) qs[tid] = q[(size_t)s * DD + h * DHH + tid];
    __syncthreads();

    for (int i = tid; i < SS; i += 128) {
        const float4* kr = (const float4*)(k + (size_t)i * DD + h * DHH);
        float dot = 0.0f;
#pragma unroll
        for (int d4 = 0; d4 < 16; d4++) {
            float4 kv = kr[d4];
            dot += qs[4 * d4 + 0] * kv.x + qs[4 * d4 + 1] * kv.y +
                   qs[4 * d4 + 2] * kv.z + qs[4 * d4 + 3] * kv.w;
        }
        sc[i] = dot;
    }
    __syncthreads();

    float mx = -1e30f;
    for (int i = tid; i < SS; i += 128) mx = fmaxf(mx, sc[i]);
    red[tid] = mx;
    __syncthreads();
    for (int st = 64; st > 0; st >>= 1) {
        if (tid < st) red[tid] = fmaxf(red[tid], red[tid + st]);
        __syncthreads();
    }
    mx = red[0];
    __syncthreads();

    float ssum = 0.0f;
    for (int i = tid; i < SS; i += 128) {
        float p = __expf(sc[i] - mx);
        sc[i] = p;
        ssum += p;
    }
    red[tid] = ssum;
    __syncthreads();
    for (int st = 64; st > 0; st >>= 1) {
        if (tid < st) red[tid] += red[tid + st];
        __syncthreads();
    }
    float inv = 1.0f / red[0];
    __syncthreads();

    int d = tid & 63;
    int half = tid >> 6;
    float acc = 0.0f;
    for (int i = half; i < SS; i += 2)
        acc = fmaf(sc[i], v[(size_t)i * DD + h * DHH + d], acc);
    pacc[half][d] = acc;
    __syncthreads();
    if (tid < DHH)
        out[(size_t)s * DD + h * DHH + tid] = (pacc[0][tid] + pacc[1][tid]) * inv;
}

// ---------------- pooling + classifier ----------------
__global__ void pool_kernel(const float* __restrict__ x, float* __restrict__ pooled) {
    int d = blockIdx.x;
    int tid = threadIdx.x;
    __shared__ float red[256];
    float sum = 0.0f;
    for (int s = tid; s < SS; s += 256) sum += x[(size_t)s * DD + d];
    red[tid] = sum;
    __syncthreads();
    for (int st = 128; st > 0; st >>= 1) {
        if (tid < st) red[tid] += red[tid + st];
        __syncthreads();
    }
    if (tid == 0) pooled[d] = red[0] * (1.0f / SS);
}

__global__ void final_kernel(const float* __restrict__ pooled,
                             const float* __restrict__ w,
                             const float* __restrict__ b,
                             float* __restrict__ out) {
    int tid = threadIdx.x;
    __shared__ float red[256];
    float sum = 0.0f;
    for (int d = tid; d < DD; d += 256) sum += pooled[d] * w[d];
    red[tid] = sum;
    __syncthreads();
    for (int st = 128; st > 0; st >>= 1) {
        if (tid < st) red[tid] += red[tid + st];
        __syncthreads();
    }
    if (tid == 0) out[0] = red[0] + b[0];
}

// ---------------- launch ----------------
extern "C" void kernel_launch(void* const* d_in, const int* in_sizes, int n_in,
                              void* d_out, int out_size) {
    const int*   ids     = (const int*)d_in[0];
    const float* emb_tok = (const float*)d_in[2];
    const float* emb_pos = (const float*)d_in[3];
    const float* ln_e_g  = (const float*)d_in[4];
    const float* ln_e_b  = (const float*)d_in[5];
    const float* wq      = (const float*)d_in[6];
    const float* bq      = (const float*)d_in[7];
    const float* wk      = (const float*)d_in[8];
    const float* bk      = (const float*)d_in[9];
    const float* wv      = (const float*)d_in[10];
    const float* bv      = (const float*)d_in[11];
    const float* wo      = (const float*)d_in[12];
    const float* bo      = (const float*)d_in[13];
    const float* ln1_g   = (const float*)d_in[14];
    const float* ln1_b   = (const float*)d_in[15];
    const float* w1      = (const float*)d_in[16];
    const float* b1      = (const float*)d_in[17];
    const float* w2m     = (const float*)d_in[18];
    const float* b2      = (const float*)d_in[19];
    const float* ln2_g   = (const float*)d_in[20];
    const float* ln2_b   = (const float*)d_in[21];
    const float* fc_w    = (const float*)d_in[22];
    const float* fc_b    = (const float*)d_in[23];

    float *x, *tmp, *q, *k, *v, *att, *h, *pooled;
    cudaGetSymbolAddress((void**)&x,      g_x);
    cudaGetSymbolAddress((void**)&tmp,    g_tmp);
    cudaGetSymbolAddress((void**)&q,      g_q);
    cudaGetSymbolAddress((void**)&k,      g_k);
    cudaGetSymbolAddress((void**)&v,      g_v);
    cudaGetSymbolAddress((void**)&att,    g_att);
    cudaGetSymbolAddress((void**)&h,      g_h);
    cudaGetSymbolAddress((void**)&pooled, g_pooled);
    float* tmp2 = tmp + (size_t)SS * DD;

    const int ASMEM = 3 * 64 * AP * sizeof(float);
    cudaFuncSetAttribute(attn_tiled, cudaFuncAttributeMaxDynamicSharedMemorySize, ASMEM);

    embed_kernel<<<SS, 256>>>(ids, emb_tok, emb_pos, tmp);
    ln_kernel<<<SS, 256>>>(tmp, nullptr, nullptr, ln_e_g, ln_e_b, x);

    dim3 gQKV(18, SS / TBM);        // (18,16) = 288 blocks
    dim3 gDs(DD / TBN, SS / TBM, 2); // (6,16,2) = 192 blocks, split-K=2
    dim3 gF(FF / TBN, SS / TBM);    // (24,16) = 384 blocks

    for (int l = 0; l < NLAYERS; l++) {
        size_t woff  = (size_t)l * DD * DD;
        size_t foff1 = (size_t)l * DD * FF;
        size_t foff2 = (size_t)l * FF * DD;

        qkv_tf32<<<gQKV, 256>>>(x, wq + woff, wk + woff, wv + woff,
                                bq + l * DD, bk + l * DD, bv + l * DD, q, k, v);

        attn_tiled<<<dim3(SS / 64, HH), 128, ASMEM>>>(q, k, v, att);
        attn_full<<<dim3(GG, HH), 128>>>(q, k, v, att);

        gemm_tf32<0><<<gDs, 256>>>(att, wo + woff, bo + l * DD, tmp, SS, DD, DD, 384);
        ln_kernel<<<SS, 256>>>(tmp, tmp2, x, ln1_g + l * DD, ln1_b + l * DD, x);

        gemm_tf32<2><<<gF, 256>>>(x, w1 + foff1, b1 + l * FF, h, SS, FF, DD, DD);
        gemm_tf32<0><<<gDs, 256>>>(h, w2m + foff2, b2 + l * DD, tmp, SS, DD, FF, 1536);
        ln_kernel<<<SS, 256>>>(tmp, tmp2, x, ln2_g + l * DD, ln2_b + l * DD, x);
    }

    pool_kernel<<<DD, 256>>>(x, pooled);
    final_kernel<<<1, 256>>>(pooled, fc_w, fc_b, (float*)d_out);
}

// round 7
// speedup vs baseline: 3.4371x; 1.0103x over previous
#include <cuda_runtime.h>
#include <math.h>
#include <stdint.h>

#define SS 2048
#define DD 768
#define HH 12
#define DHH 64
#define FF 3072
#define GG 16
#define W2W 256
#define NLAYERS 2

// ---------------- scratch (static device globals; no allocation) ----------------
__device__ float g_x[SS * DD];
__device__ float g_tmp[2 * SS * DD];   // split-K partials [part0 | part1]
__device__ float g_q[SS * DD];
__device__ float g_k[SS * DD];
__device__ float g_v[SS * DD];
__device__ float g_att[SS * DD];
__device__ float g_h[SS * FF];
__device__ float g_pooled[DD];

// ---------------- embedding ----------------
__global__ void embed_kernel(const int* __restrict__ ids,
                             const float* __restrict__ tok,
                             const float* __restrict__ pos,
                             float* __restrict__ out) {
    int s = blockIdx.x;
    int id = ids[s];
    const float* trow = tok + (size_t)id * DD;
    const float* prow = pos + (size_t)s * DD;
    float* orow = out + (size_t)s * DD;
    for (int d = threadIdx.x; d < DD; d += blockDim.x)
        orow[d] = trow[d] + prow[d];
}

// ---------------- layernorm (round-5 numerics: 256 threads, smem tree) ----------------
__global__ void ln_kernel(const float* __restrict__ inp,
                          const float* __restrict__ inp2,
                          const float* __restrict__ resid,
                          const float* __restrict__ gw,
                          const float* __restrict__ bw,
                          float* __restrict__ out) {
    int s = blockIdx.x;
    int tid = threadIdx.x;
    __shared__ float red[256];

    float vloc[3];
    float sum = 0.0f;
#pragma unroll
    for (int i = 0; i < 3; i++) {
        int d = tid + i * 256;
        float val = inp[(size_t)s * DD + d];
        if (inp2)  val += inp2[(size_t)s * DD + d];
        if (resid) val += resid[(size_t)s * DD + d];
        vloc[i] = val;
        sum += val;
    }
    red[tid] = sum;
    __syncthreads();
    for (int st = 128; st > 0; st >>= 1) {
        if (tid < st) red[tid] += red[tid + st];
        __syncthreads();
    }
    float mean = red[0] * (1.0f / DD);
    __syncthreads();

    float vs = 0.0f;
#pragma unroll
    for (int i = 0; i < 3; i++) {
        float dd = vloc[i] - mean;
        vs += dd * dd;
    }
    red[tid] = vs;
    __syncthreads();
    for (int st = 128; st > 0; st >>= 1) {
        if (tid < st) red[tid] += red[tid + st];
        __syncthreads();
    }
    float rstd = rsqrtf(red[0] * (1.0f / DD) + 1e-5f);

#pragma unroll
    for (int i = 0; i < 3; i++) {
        int d = tid + i * 256;
        out[(size_t)s * DD + d] = (vloc[i] - mean) * rstd * gw[d] + bw[d];
    }
}

// ================= TF32 tensor-core GEMM (double-buffered smem) =================
#define TBM 128
#define TBN 128
#define TBK 16
#define TST 136

__device__ __forceinline__ uint32_t f2tf32(float x) {
    uint32_t t;
    asm("cvt.rna.tf32.f32 %0, %1;" : "=r"(t) : "f"(x));
    return t;
}

__device__ __forceinline__ void mma_tf32(float* c,
                                         uint32_t a0, uint32_t a1, uint32_t a2, uint32_t a3,
                                         uint32_t b0, uint32_t b1) {
    asm volatile(
        "mma.sync.aligned.m16n8k8.row.col.f32.tf32.tf32.f32 "
        "{%0,%1,%2,%3}, {%4,%5,%6,%7}, {%8,%9}, {%0,%1,%2,%3};"
        : "+f"(c[0]), "+f"(c[1]), "+f"(c[2]), "+f"(c[3])
        : "r"(a0), "r"(a1), "r"(a2), "r"(a3), "r"(b0), "r"(b1));
}

__device__ __forceinline__ void tf32_mainloop(
    const float* __restrict__ A, const float* __restrict__ B,
    int K, int N, int bm, int bn, int kStart, int kEnd,
    uint32_t (*As)[TBK][TST], uint32_t (*Bs)[TBK][TST], float acc[2][8][4]) {

    int tid = threadIdx.x;
    int lane = tid & 31;
    int wid = tid >> 5;
    int wm = wid >> 1;
    int wn = wid & 1;
    int grp = lane >> 2;
    int tig = lane & 3;

    int ra = tid >> 1,  ca = (tid & 1) * 8;
    int rb = tid >> 4,  cb = (tid & 15) * 8;

    float4 pa0, pa1, pb0, pb1;
    pa0 = *(const float4*)&A[(size_t)(bm + ra) * K + kStart + ca];
    pa1 = *(const float4*)&A[(size_t)(bm + ra) * K + kStart + ca + 4];
    pb0 = *(const float4*)&B[(size_t)(kStart + rb) * N + bn + cb];
    pb1 = *(const float4*)&B[(size_t)(kStart + rb) * N + bn + cb + 4];

    // stage 0
    {
        uint32_t (*Asb)[TST] = As[0];
        uint32_t (*Bsb)[TST] = Bs[0];
        Asb[ca + 0][ra] = f2tf32(pa0.x); Asb[ca + 1][ra] = f2tf32(pa0.y);
        Asb[ca + 2][ra] = f2tf32(pa0.z); Asb[ca + 3][ra] = f2tf32(pa0.w);
        Asb[ca + 4][ra] = f2tf32(pa1.x); Asb[ca + 5][ra] = f2tf32(pa1.y);
        Asb[ca + 6][ra] = f2tf32(pa1.z); Asb[ca + 7][ra] = f2tf32(pa1.w);
        Bsb[rb][cb + 0] = f2tf32(pb0.x); Bsb[rb][cb + 1] = f2tf32(pb0.y);
        Bsb[rb][cb + 2] = f2tf32(pb0.z); Bsb[rb][cb + 3] = f2tf32(pb0.w);
        Bsb[rb][cb + 4] = f2tf32(pb1.x); Bsb[rb][cb + 5] = f2tf32(pb1.y);
        Bsb[rb][cb + 6] = f2tf32(pb1.z); Bsb[rb][cb + 7] = f2tf32(pb1.w);
    }
    __syncthreads();

    int nIter = (kEnd - kStart) / TBK;
    for (int it = 0; it < nIter; it++) {
        int buf = it & 1;
        bool more = (it + 1 < nIter);
        if (more) {
            int kn = kStart + (it + 1) * TBK;
            pa0 = *(const float4*)&A[(size_t)(bm + ra) * K + kn + ca];
            pa1 = *(const float4*)&A[(size_t)(bm + ra) * K + kn + ca + 4];
            pb0 = *(const float4*)&B[(size_t)(kn + rb) * N + bn + cb];
            pb1 = *(const float4*)&B[(size_t)(kn + rb) * N + bn + cb + 4];
        }

        uint32_t (*Asb)[TST] = As[buf];
        uint32_t (*Bsb)[TST] = Bs[buf];
#pragma unroll
        for (int ks = 0; ks < 2; ks++) {
            int kb = ks * 8;
            uint32_t af[2][4];
#pragma unroll
            for (int mi = 0; mi < 2; mi++) {
                int m = wm * 32 + mi * 16 + grp;
                af[mi][0] = Asb[kb + tig][m];
                af[mi][1] = Asb[kb + tig][m + 8];
                af[mi][2] = Asb[kb + tig + 4][m];
                af[mi][3] = Asb[kb + tig + 4][m + 8];
            }
            uint32_t bf[8][2];
#pragma unroll
            for (int ni = 0; ni < 8; ni++) {
                int n = wn * 64 + ni * 8 + grp;
                bf[ni][0] = Bsb[kb + tig][n];
                bf[ni][1] = Bsb[kb + tig + 4][n];
            }
#pragma unroll
            for (int mi = 0; mi < 2; mi++)
#pragma unroll
                for (int ni = 0; ni < 8; ni++)
                    mma_tf32(acc[mi][ni], af[mi][0], af[mi][1], af[mi][2], af[mi][3],
                             bf[ni][0], bf[ni][1]);
        }

        if (more) {
            uint32_t (*Asn)[TST] = As[buf ^ 1];
            uint32_t (*Bsn)[TST] = Bs[buf ^ 1];
            Asn[ca + 0][ra] = f2tf32(pa0.x); Asn[ca + 1][ra] = f2tf32(pa0.y);
            Asn[ca + 2][ra] = f2tf32(pa0.z); Asn[ca + 3][ra] = f2tf32(pa0.w);
            Asn[ca + 4][ra] = f2tf32(pa1.x); Asn[ca + 5][ra] = f2tf32(pa1.y);
            Asn[ca + 6][ra] = f2tf32(pa1.z); Asn[ca + 7][ra] = f2tf32(pa1.w);
            Bsn[rb][cb + 0] = f2tf32(pb0.x); Bsn[rb][cb + 1] = f2tf32(pb0.y);
            Bsn[rb][cb + 2] = f2tf32(pb0.z); Bsn[rb][cb + 3] = f2tf32(pb0.w);
            Bsn[rb][cb + 4] = f2tf32(pb1.x); Bsn[rb][cb + 5] = f2tf32(pb1.y);
            Bsn[rb][cb + 6] = f2tf32(pb1.z); Bsn[rb][cb + 7] = f2tf32(pb1.w);
        }
        __syncthreads();
    }
}

__device__ __forceinline__ float gelu_f(float v) {
    float x3 = v * v * v;
    return 0.5f * v * (1.0f + tanhf(0.7978845608028654f * (v + 0.044715f * x3)));
}

template <int EPI>
__global__ void __launch_bounds__(256)
gemm_tf32(const float* __restrict__ A, const float* __restrict__ B,
          const float* __restrict__ bias, float* __restrict__ C,
          int M, int N, int K, int ksplit) {
    __shared__ uint32_t As[2][TBK][TST];
    __shared__ uint32_t Bs[2][TBK][TST];

    int bm = blockIdx.y * TBM;
    int bn = blockIdx.x * TBN;
    int z = blockIdx.z;
    int kStart = z * ksplit;
    int kEnd = min(K, kStart + ksplit);
    C += (size_t)z * M * N;

    float acc[2][8][4];
#pragma unroll
    for (int mi = 0; mi < 2; mi++)
#pragma unroll
        for (int ni = 0; ni < 8; ni++)
#pragma unroll
            for (int c = 0; c < 4; c++) acc[mi][ni][c] = 0.0f;

    tf32_mainloop(A, B, K, N, bm, bn, kStart, kEnd, As, Bs, acc);

    int lane = threadIdx.x & 31;
    int wid = threadIdx.x >> 5;
    int wm = wid >> 1, wn = wid & 1;
    int grp = lane >> 2, tig = lane & 3;

#pragma unroll
    for (int mi = 0; mi < 2; mi++) {
        int row = bm + wm * 32 + mi * 16 + grp;
#pragma unroll
        for (int ni = 0; ni < 8; ni++) {
            int col = bn + wn * 64 + ni * 8 + tig * 2;
            float b0 = 0.0f, b1 = 0.0f;
            if (z == 0) { b0 = bias[col]; b1 = bias[col + 1]; }
            float v0 = acc[mi][ni][0] + b0;
            float v1 = acc[mi][ni][1] + b1;
            float v2 = acc[mi][ni][2] + b0;
            float v3 = acc[mi][ni][3] + b1;
            if (EPI == 2) { v0 = gelu_f(v0); v1 = gelu_f(v1); v2 = gelu_f(v2); v3 = gelu_f(v3); }
            *(float2*)&C[(size_t)row * N + col]       = make_float2(v0, v1);
            *(float2*)&C[(size_t)(row + 8) * N + col] = make_float2(v2, v3);
        }
    }
}

__global__ void __launch_bounds__(256)
qkv_tf32(const float* __restrict__ X,
         const float* __restrict__ Wq, const float* __restrict__ Wk, const float* __restrict__ Wv,
         const float* __restrict__ Bq, const float* __restrict__ Bk, const float* __restrict__ Bv,
         float* __restrict__ Q, float* __restrict__ Ko, float* __restrict__ V) {
    __shared__ uint32_t As[2][TBK][TST];
    __shared__ uint32_t Bs[2][TBK][TST];

    int bm = blockIdx.y * TBM;
    int which = blockIdx.x / 6;
    int bn = (blockIdx.x % 6) * TBN;

    const float* B   = (which == 0) ? Wq : (which == 1) ? Wk : Wv;
    const float* bia = (which == 0) ? Bq : (which == 1) ? Bk : Bv;
    float*       C   = (which == 0) ? Q  : (which == 1) ? Ko : V;
    float scale = (which == 0) ? 0.125f : 1.0f;

    float acc[2][8][4];
#pragma unroll
    for (int mi = 0; mi < 2; mi++)
#pragma unroll
        for (int ni = 0; ni < 8; ni++)
#pragma unroll
            for (int c = 0; c < 4; c++) acc[mi][ni][c] = 0.0f;

    tf32_mainloop(X, B, DD, DD, bm, bn, 0, DD, As, Bs, acc);

    int lane = threadIdx.x & 31;
    int wid = threadIdx.x >> 5;
    int wm = wid >> 1, wn = wid & 1;
    int grp = lane >> 2, tig = lane & 3;

#pragma unroll
    for (int mi = 0; mi < 2; mi++) {
        int row = bm + wm * 32 + mi * 16 + grp;
#pragma unroll
        for (int ni = 0; ni < 8; ni++) {
            int col = bn + wn * 64 + ni * 8 + tig * 2;
            float b0 = bia[col], b1 = bia[col + 1];
            float v0 = (acc[mi][ni][0] + b0) * scale;
            float v1 = (acc[mi][ni][1] + b1) * scale;
            float v2 = (acc[mi][ni][2] + b0) * scale;
            float v3 = (acc[mi][ni][3] + b1) * scale;
            *(float2*)&C[(size_t)row * DD + col]       = make_float2(v0, v1);
            *(float2*)&C[(size_t)(row + 8) * DD + col] = make_float2(v2, v3);
        }
    }
}

// ---------------- tiled local+global attention (round-5 numerics, fp32) ----------------
#define AP 68

__global__ void __launch_bounds__(128)
attn_tiled(const float* __restrict__ q, const float* __restrict__ k,
           const float* __restrict__ v, float* __restrict__ out) {
    extern __shared__ float smem[];
    float (*Qs)[AP] = (float(*)[AP])smem;
    float (*KP)[AP] = (float(*)[AP])(smem + 64 * AP);
    float (*Vs)[AP] = (float(*)[AP])(smem + 2 * 64 * AP);

    int tid = threadIdx.x;
    int h = blockIdx.y;
    int q0 = blockIdx.x * 64;
    int ty = tid >> 3;
    int tx = tid & 7;

    int lo = max(GG, q0 - W2W);
    int hi = min(SS - 1, q0 + 63 + W2W);
    int nk = GG + (hi - lo + 1);
    int ntiles = (nk + 63) >> 6;

#pragma unroll
    for (int j4 = 0; j4 < 8; j4++) {
        int lin = tid + j4 * 128;
        int ql = lin >> 4;
        int dp = (lin & 15) * 4;
        float4 qv = *(const float4*)&q[(size_t)(q0 + ql) * DD + h * DHH + dp];
        Qs[dp + 0][ql] = qv.x; Qs[dp + 1][ql] = qv.y;
        Qs[dp + 2][ql] = qv.z; Qs[dp + 3][ql] = qv.w;
    }

    float m[4], l[4], O[4][8];
#pragma unroll
    for (int i = 0; i < 4; i++) { m[i] = -1e30f; l[i] = 0.0f; }
#pragma unroll
    for (int i = 0; i < 4; i++)
#pragma unroll
        for (int j = 0; j < 8; j++) O[i][j] = 0.0f;

    for (int t = 0; t < ntiles; t++) {
        int ibase = t * 64;
#pragma unroll
        for (int j4 = 0; j4 < 8; j4++) {
            int lin = tid + j4 * 128;
            int kl = lin >> 4;
            int dp = (lin & 15) * 4;
            int i = ibase + kl;
            float4 kv = make_float4(0.f, 0.f, 0.f, 0.f);
            float4 vv = make_float4(0.f, 0.f, 0.f, 0.f);
            if (i < nk) {
                int kk = (i < GG) ? i : lo - GG + i;
                kv = *(const float4*)&k[(size_t)kk * DD + h * DHH + dp];
                vv = *(const float4*)&v[(size_t)kk * DD + h * DHH + dp];
            }
            KP[dp + 0][kl] = kv.x; KP[dp + 1][kl] = kv.y;
            KP[dp + 2][kl] = kv.z; KP[dp + 3][kl] = kv.w;
            *(float4*)&Vs[kl][dp] = vv;
        }
        __syncthreads();

        float sacc[4][8] = {};
#pragma unroll
        for (int d = 0; d < 64; d++) {
            float a[4], b[8];
            *(float4*)&a[0] = *(const float4*)&Qs[d][ty * 4];
            *(float4*)&b[0] = *(const float4*)&KP[d][tx * 8];
            *(float4*)&b[4] = *(const float4*)&KP[d][tx * 8 + 4];
#pragma unroll
            for (int i = 0; i < 4; i++)
#pragma unroll
                for (int j = 0; j < 8; j++)
                    sacc[i][j] = fmaf(a[i], b[j], sacc[i][j]);
        }
        __syncthreads();

#pragma unroll
        for (int i = 0; i < 4; i++) {
            int s = q0 + ty * 4 + i;
#pragma unroll
            for (int j = 0; j < 8; j++) {
                int idx = ibase + tx * 8 + j;
                int kk = (idx < GG) ? idx : lo - GG + idx;
                int dk = kk - s;
                bool valid = (idx < nk) && ((idx < GG) || (dk <= W2W && dk >= -W2W));
                if (!valid) sacc[i][j] = -1e30f;
            }
            float rmax = sacc[i][0];
#pragma unroll
            for (int j = 1; j < 8; j++) rmax = fmaxf(rmax, sacc[i][j]);
#pragma unroll
            for (int o = 1; o < 8; o <<= 1)
                rmax = fmaxf(rmax, __shfl_xor_sync(0xffffffff, rmax, o));
            float mn = fmaxf(m[i], rmax);
            float fac = __expf(m[i] - mn);
            float rsum = 0.0f;
#pragma unroll
            for (int j = 0; j < 8; j++) {
                float p = __expf(sacc[i][j] - mn);
                sacc[i][j] = p;
                rsum += p;
            }
#pragma unroll
            for (int o = 1; o < 8; o <<= 1)
                rsum += __shfl_xor_sync(0xffffffff, rsum, o);
            l[i] = l[i] * fac + rsum;
            m[i] = mn;
#pragma unroll
            for (int j = 0; j < 8; j++) O[i][j] *= fac;
        }

#pragma unroll
        for (int j = 0; j < 8; j++)
#pragma unroll
            for (int i = 0; i < 4; i++)
                KP[tx * 8 + j][ty * 4 + i] = sacc[i][j];
        __syncthreads();

#pragma unroll
        for (int kl = 0; kl < 64; kl++) {
            float a[4], b[8];
            *(float4*)&a[0] = *(const float4*)&KP[kl][ty * 4];
            *(float4*)&b[0] = *(const float4*)&Vs[kl][tx * 8];
            *(float4*)&b[4] = *(const float4*)&Vs[kl][tx * 8 + 4];
#pragma unroll
            for (int i = 0; i < 4; i++)
#pragma unroll
                for (int j = 0; j < 8; j++)
                    O[i][j] = fmaf(a[i], b[j], O[i][j]);
        }
        __syncthreads();
    }

#pragma unroll
    for (int i = 0; i < 4; i++) {
        int s = q0 + ty * 4 + i;
        if (s < GG) continue;
        float inv = 1.0f / l[i];
        float o[8];
#pragma unroll
        for (int j = 0; j < 8; j++) o[j] = O[i][j] * inv;
        float* orow = &out[(size_t)s * DD + h * DHH + tx * 8];
        *(float4*)&orow[0] = *(float4*)&o[0];
        *(float4*)&orow[4] = *(float4*)&o[4];
    }
}

// ---------------- full attention for global queries (s < G) ----------------
__global__ void __launch_bounds__(128)
attn_full(const float* __restrict__ q, const float* __restrict__ k,
          const float* __restrict__ v, float* __restrict__ out) {
    int s = blockIdx.x;
    int h = blockIdx.y;
    int tid = threadIdx.x;

    __shared__ float sc[SS];
    __shared__ float qs[DHH];
    __shared__ float red[128];
    __shared__ float pacc[2][DHH];

    if (tid < DHH) qs[tid] = q[(size_t)s * DD + h * DHH + tid];
    __syncthreads();

    for (int i = tid; i < SS; i += 128) {
        const float4* kr = (const float4*)(k + (size_t)i * DD + h * DHH);
        float dot = 0.0f;
#pragma unroll
        for (int d4 = 0; d4 < 16; d4++) {
            float4 kv = kr[d4];
            dot += qs[4 * d4 + 0] * kv.x + qs[4 * d4 + 1] * kv.y +
                   qs[4 * d4 + 2] * kv.z + qs[4 * d4 + 3] * kv.w;
        }
        sc[i] = dot;
    }
    __syncthreads();

    float mx = -1e30f;
    for (int i = tid; i < SS; i += 128) mx = fmaxf(mx, sc[i]);
    red[tid] = mx;
    __syncthreads();
    for (int st = 64; st > 0; st >>= 1) {
        if (tid < st) red[tid] = fmaxf(red[tid], red[tid + st]);
        __syncthreads();
    }
    mx = red[0];
    __syncthreads();

    float ssum = 0.0f;
    for (int i = tid; i < SS; i += 128) {
        float p = __expf(sc[i] - mx);
        sc[i] = p;
        ssum += p;
    }
    red[tid] = ssum;
    __syncthreads();
    for (int st = 64; st > 0; st >>= 1) {
        if (tid < st) red[tid] += red[tid + st];
        __syncthreads();
    }
    float inv = 1.0f / red[0];
    __syncthreads();

    int d = tid & 63;
    int half = tid >> 6;
    float acc = 0.0f;
    for (int i = half; i < SS; i += 2)
        acc = fmaf(sc[i], v[(size_t)i * DD + h * DHH + d], acc);
    pacc[half][d] = acc;
    __syncthreads();
    if (tid < DHH)
        out[(size_t)s * DD + h * DHH + tid] = (pacc[0][tid] + pacc[1][tid]) * inv;
}

// ---------------- pooling + classifier ----------------
__global__ void pool_kernel(const float* __restrict__ x, float* __restrict__ pooled) {
    int d = blockIdx.x;
    int tid = threadIdx.x;
    __shared__ float red[256];
    float sum = 0.0f;
    for (int s = tid; s < SS; s += 256) sum += x[(size_t)s * DD + d];
    red[tid] = sum;
    __syncthreads();
    for (int st = 128; st > 0; st >>= 1) {
        if (tid < st) red[tid] += red[tid + st];
        __syncthreads();
    }
    if (tid == 0) pooled[d] = red[0] * (1.0f / SS);
}

__global__ void final_kernel(const float* __restrict__ pooled,
                             const float* __restrict__ w,
                             const float* __restrict__ b,
                             float* __restrict__ out) {
    int tid = threadIdx.x;
    __shared__ float red[256];
    float sum = 0.0f;
    for (int d = tid; d < DD; d += 256) sum += pooled[d] * w[d];
    red[tid] = sum;
    __syncthreads();
    for (int st = 128; st > 0; st >>= 1) {
        if (tid < st) red[tid] += red[tid + st];
        __syncthreads();
    }
    if (tid == 0) out[0] = red[0] + b[0];
}

// ---------------- launch ----------------
extern "C" void kernel_launch(void* const* d_in, const int* in_sizes, int n_in,
                              void* d_out, int out_size) {
    const int*   ids     = (const int*)d_in[0];
    const float* emb_tok = (const float*)d_in[2];
    const float* emb_pos = (const float*)d_in[3];
    const float* ln_e_g  = (const float*)d_in[4];
    const float* ln_e_b  = (const float*)d_in[5];
    const float* wq      = (const float*)d_in[6];
    const float* bq      = (const float*)d_in[7];
    const float* wk      = (const float*)d_in[8];
    const float* bk      = (const float*)d_in[9];
    const float* wv      = (const float*)d_in[10];
    const float* bv      = (const float*)d_in[11];
    const float* wo      = (const float*)d_in[12];
    const float* bo      = (const float*)d_in[13];
    const float* ln1_g   = (const float*)d_in[14];
    const float* ln1_b   = (const float*)d_in[15];
    const float* w1      = (const float*)d_in[16];
    const float* b1      = (const float*)d_in[17];
    const float* w2m     = (const float*)d_in[18];
    const float* b2      = (const float*)d_in[19];
    const float* ln2_g   = (const float*)d_in[20];
    const float* ln2_b   = (const float*)d_in[21];
    const float* fc_w    = (const float*)d_in[22];
    const float* fc_b    = (const float*)d_in[23];

    float *x, *tmp, *q, *k, *v, *att, *h, *pooled;
    cudaGetSymbolAddress((void**)&x,      g_x);
    cudaGetSymbolAddress((void**)&tmp,    g_tmp);
    cudaGetSymbolAddress((void**)&q,      g_q);
    cudaGetSymbolAddress((void**)&k,      g_k);
    cudaGetSymbolAddress((void**)&v,      g_v);
    cudaGetSymbolAddress((void**)&att,    g_att);
    cudaGetSymbolAddress((void**)&h,      g_h);
    cudaGetSymbolAddress((void**)&pooled, g_pooled);
    float* tmp2 = tmp + (size_t)SS * DD;

    const int ASMEM = 3 * 64 * AP * sizeof(float);
    cudaFuncSetAttribute(attn_tiled, cudaFuncAttributeMaxDynamicSharedMemorySize, ASMEM);

    embed_kernel<<<SS, 256>>>(ids, emb_tok, emb_pos, tmp);
    ln_kernel<<<SS, 256>>>(tmp, nullptr, nullptr, ln_e_g, ln_e_b, x);

    dim3 gQKV(18, SS / TBM);          // 288 blocks
    dim3 gDs(DD / TBN, SS / TBM, 2);  // 192 blocks, split-K=2
    dim3 gF(FF / TBN, SS / TBM);      // 384 blocks

    for (int l = 0; l < NLAYERS; l++) {
        size_t woff  = (size_t)l * DD * DD;
        size_t foff1 = (size_t)l * DD * FF;
        size_t foff2 = (size_t)l * FF * DD;

        qkv_tf32<<<gQKV, 256>>>(x, wq + woff, wk + woff, wv + woff,
                                bq + l * DD, bk + l * DD, bv + l * DD, q, k, v);

        attn_tiled<<<dim3(SS / 64, HH), 128, ASMEM>>>(q, k, v, att);
        attn_full<<<dim3(GG, HH), 128>>>(q, k, v, att);

        gemm_tf32<0><<<gDs, 256>>>(att, wo + woff, bo + l * DD, tmp, SS, DD, DD, 384);
        ln_kernel<<<SS, 256>>>(tmp, tmp2, x, ln1_g + l * DD, ln1_b + l * DD, x);

        gemm_tf32<2><<<gF, 256>>>(x, w1 + foff1, b1 + l * FF, h, SS, FF, DD, DD);
        gemm_tf32<0><<<gDs, 256>>>(h, w2m + foff2, b2 + l * DD, tmp, SS, DD, FF, 1536);
        ln_kernel<<<SS, 256>>>(tmp, tmp2, x, ln2_g + l * DD, ln2_b + l * DD, x);
    }

    pool_kernel<<<DD, 256>>>(x, pooled);
    final_kernel<<<1, 256>>>(pooled, fc_w, fc_b, (float*)d_out);
}